// round 1
// baseline (speedup 1.0000x reference)
#include <cuda_runtime.h>
#include <math.h>

// ---------------- problem constants ----------------
#define NTOK   2048          // B*S
#define ECFG   768
#define SCFG   1024
#define HCFG   12
#define DCFG   64
#define BHCFG  24            // B*H
#define MCFG   768
#define QMCFG  3072          // Q*M
#define H1C    771           // used fc1 columns (M + Q - 1)
#define H1LD   772           // padded stride

// ---------------- scratch (device globals; no allocs allowed) ----------------
__device__ float g_h   [NTOK * ECFG];
__device__ float g_q   [BHCFG * SCFG * DCFG];
__device__ float g_k   [BHCFG * SCFG * DCFG];
__device__ float g_v   [BHCFG * SCFG * DCFG];
__device__ float g_qn  [BHCFG * SCFG];
__device__ float g_kn  [BHCFG * SCFG];
__device__ float g_P   [(size_t)BHCFG * SCFG * SCFG];   // raw dots -> mixed probs
__device__ float g_vals[NTOK * ECFG];
__device__ float g_x1  [NTOK * ECFG];
__device__ float g_y   [NTOK * ECFG];
__device__ float g_h1  [NTOK * H1LD];
__device__ float g_z   [NTOK * QMCFG];

// ---------------- block reductions (blockDim.x == 256) ----------------
__device__ __forceinline__ float block_reduce_sum(float v, float* sbuf) {
#pragma unroll
    for (int o = 16; o > 0; o >>= 1) v += __shfl_xor_sync(0xffffffffu, v, o);
    int w = threadIdx.x >> 5, l = threadIdx.x & 31;
    __syncthreads();
    if (l == 0) sbuf[w] = v;
    __syncthreads();
    if (threadIdx.x < 32) {
        float t = (l < 8) ? sbuf[l] : 0.f;
#pragma unroll
        for (int o = 4; o > 0; o >>= 1) t += __shfl_xor_sync(0xffffffffu, t, o);
        if (l == 0) sbuf[32] = t;
    }
    __syncthreads();
    return sbuf[32];
}

__device__ __forceinline__ float block_reduce_max(float v, float* sbuf) {
#pragma unroll
    for (int o = 16; o > 0; o >>= 1) v = fmaxf(v, __shfl_xor_sync(0xffffffffu, v, o));
    int w = threadIdx.x >> 5, l = threadIdx.x & 31;
    __syncthreads();
    if (l == 0) sbuf[w] = v;
    __syncthreads();
    if (threadIdx.x < 32) {
        float t = (l < 8) ? sbuf[l] : -1e30f;
#pragma unroll
        for (int o = 4; o > 0; o >>= 1) t = fmaxf(t, __shfl_xor_sync(0xffffffffu, t, o));
        if (l == 0) sbuf[32] = t;
    }
    __syncthreads();
    return sbuf[32];
}

// ---------------- layernorm: one block per row of 768 ----------------
__global__ void __launch_bounds__(256) ln_kernel(const float* __restrict__ x,
                                                 const float* __restrict__ w,
                                                 const float* __restrict__ b,
                                                 float* __restrict__ out) {
    __shared__ float sbuf[34];
    const int row = blockIdx.x;
    const float* xr = x + (size_t)row * ECFG;
    float v[3];
    float s = 0.f, sq = 0.f;
#pragma unroll
    for (int u = 0; u < 3; ++u) {
        v[u] = xr[threadIdx.x + u * 256];
        s += v[u];
        sq += v[u] * v[u];
    }
    s  = block_reduce_sum(s, sbuf);
    sq = block_reduce_sum(sq, sbuf);
    const float mean = s * (1.0f / ECFG);
    const float var  = sq * (1.0f / ECFG) - mean * mean;
    const float inv  = rsqrtf(var + 1e-5f);
    float* orow = out + (size_t)row * ECFG;
#pragma unroll
    for (int u = 0; u < 3; ++u) {
        int e = threadIdx.x + u * 256;
        orow[e] = (v[u] - mean) * inv * w[e] + b[e];
    }
}

// ---------------- generic GEMM: C[n,co] = sum_k A[n,k]*W[co,k] (+bias)(+resid) ----
// 64x64 tile, BK=16, 256 threads, 4x4 per-thread microtile, float4 smem fragments.
// outMode 0: C[z*sCb + n*ldc + co]
// outMode 1: "bhsd" remap -> C[((b*12+h)*1024+s)*64+d]  (z==0 only)
__global__ void __launch_bounds__(256) gemm_nt(
    const float* __restrict__ A, int lda, long long sAb,
    const float* __restrict__ W, int ldw, long long sWb,
    const float* __restrict__ bias,
    const float* __restrict__ resid, int ldr,
    float* __restrict__ C, int ldc, long long sCb,
    int N, int Co, int K, int outMode)
{
    __shared__ float As[16][68];
    __shared__ float Ws[16][68];
    const int tid = threadIdx.x;
    const int tx = tid & 15, ty = tid >> 4;
    const int rowBase = blockIdx.y * 64;
    const int colBase = blockIdx.x * 64;
    const float* Ab = A + (size_t)blockIdx.z * sAb;
    const float* Wb = W + (size_t)blockIdx.z * sWb;
    float acc[4][4] = {};

    const int lr = tid >> 2;        // 0..63
    const int lc = (tid & 3) * 4;   // 0,4,8,12

    for (int k0 = 0; k0 < K; k0 += 16) {
        {
            const int gr = rowBase + lr;
            float4 av = make_float4(0.f, 0.f, 0.f, 0.f);
            if (gr < N) av = *reinterpret_cast<const float4*>(Ab + (size_t)gr * lda + k0 + lc);
            As[lc + 0][lr] = av.x; As[lc + 1][lr] = av.y;
            As[lc + 2][lr] = av.z; As[lc + 3][lr] = av.w;
            const int gw = colBase + lr;
            float4 wv = make_float4(0.f, 0.f, 0.f, 0.f);
            if (gw < Co) wv = *reinterpret_cast<const float4*>(Wb + (size_t)gw * ldw + k0 + lc);
            Ws[lc + 0][lr] = wv.x; Ws[lc + 1][lr] = wv.y;
            Ws[lc + 2][lr] = wv.z; Ws[lc + 3][lr] = wv.w;
        }
        __syncthreads();
#pragma unroll
        for (int kk = 0; kk < 16; ++kk) {
            const float4 a0 = *reinterpret_cast<const float4*>(&As[kk][ty * 4]);
            const float4 w0 = *reinterpret_cast<const float4*>(&Ws[kk][tx * 4]);
            const float a[4] = {a0.x, a0.y, a0.z, a0.w};
            const float w[4] = {w0.x, w0.y, w0.z, w0.w};
#pragma unroll
            for (int i = 0; i < 4; ++i)
#pragma unroll
                for (int j = 0; j < 4; ++j)
                    acc[i][j] = fmaf(a[i], w[j], acc[i][j]);
        }
        __syncthreads();
    }

#pragma unroll
    for (int i = 0; i < 4; ++i) {
        const int gr = rowBase + ty * 4 + i;
        if (gr >= N) continue;
#pragma unroll
        for (int j = 0; j < 4; ++j) {
            const int gc = colBase + tx * 4 + j;
            if (gc >= Co) continue;
            float v = acc[i][j];
            if (bias)  v += bias[gc];
            if (resid) v += resid[(size_t)gr * ldr + gc];
            if (outMode == 0) {
                C[(size_t)blockIdx.z * sCb + (size_t)gr * ldc + gc] = v;
            } else {
                const int b = gr >> 10, s = gr & 1023;
                const int h = gc >> 6, d = gc & 63;
                C[(((size_t)(b * HCFG + h)) * SCFG + s) * DCFG + d] = v;
            }
        }
    }
}

// ---------------- row norms of [rows][64] ----------------
__global__ void norm_kernel(const float* __restrict__ src, float* __restrict__ dst, int nrows) {
    const int r = blockIdx.x * blockDim.x + threadIdx.x;
    if (r >= nrows) return;
    const float4* p = reinterpret_cast<const float4*>(src + (size_t)r * DCFG);
    float s = 0.f;
#pragma unroll
    for (int i = 0; i < 16; ++i) {
        float4 t = p[i];
        s += t.x * t.x + t.y * t.y + t.z * t.z + t.w * t.w;
    }
    dst[r] = s;
}

// ---------------- softmax + RBF mix, in place on raw dot rows ----------------
__global__ void __launch_bounds__(256) mix_kernel(float* __restrict__ P,
                                                  const float* __restrict__ qn_,
                                                  const float* __restrict__ kn_,
                                                  const float* __restrict__ pond) {
    __shared__ float sbuf[34];
    const int row = blockIdx.x;             // bh*1024 + i
    const int bh  = row >> 10;
    float* prow = P + (size_t)row * SCFG;
    const float* knb = kn_ + (size_t)bh * SCFG;
    const int tid = threadIdx.x;

    const float qn = qn_[row];
    const float sigma2 = fminf(fmaxf(qn, 1e-8f), 1e4f);

    float4 dt  = *reinterpret_cast<const float4*>(prow + tid * 4);
    float4 kn4 = *reinterpret_cast<const float4*>(knb + tid * 4);
    const float d[4]  = {dt.x, dt.y, dt.z, dt.w};
    const float kn[4] = {kn4.x, kn4.y, kn4.z, kn4.w};

    float lm = -1e30f;
#pragma unroll
    for (int u = 0; u < 4; ++u) lm = fmaxf(lm, d[u] * 0.125f);
    const float M = block_reduce_max(lm, sbuf);

    float e[4], rb[4];
    float se = 0.f, sr = 0.f;
#pragma unroll
    for (int u = 0; u < 4; ++u) {
        e[u] = expf(d[u] * 0.125f - M);
        se += e[u];
        const float d2 = fmaxf(qn + kn[u] - 2.f * d[u], 0.f);
        rb[u] = expf(-d2 / sigma2);
        sr += rb[u];
    }
    const float Ls = block_reduce_sum(se, sbuf);
    const float Lr = block_reduce_sum(sr, sbuf);

    const float sv = 1.f / (1.f + expf(-pond[0]));
    const float p0 = 1.f - sv, p1 = sv;
    const float inv = 1.f / (p0 + p1 + 1e-7f);
    const float ca = p0 * inv / Ls;
    const float cb = p1 * inv / fmaxf(Lr, 1e-8f);

    float4 o;
    o.x = ca * e[0] + cb * rb[0];
    o.y = ca * e[1] + cb * rb[1];
    o.z = ca * e[2] + cb * rb[2];
    o.w = ca * e[3] + cb * rb[3];
    *reinterpret_cast<float4*>(prow + tid * 4) = o;
}

// ---------------- P @ V (B non-transposed), per (b,h) batch ----------------
__global__ void __launch_bounds__(256) gemm_pv(const float* __restrict__ P,
                                               const float* __restrict__ V,
                                               float* __restrict__ vals) {
    __shared__ float As[16][68];
    __shared__ float Bs[16][68];
    const int bh = blockIdx.z;
    const int b = bh / HCFG, h = bh % HCFG;
    const float* Ab = P + ((size_t)bh << 20);          // bh * 1024 * 1024
    const float* Bv = V + (size_t)bh * SCFG * DCFG;    // [1024][64]
    const int tid = threadIdx.x;
    const int tx = tid & 15, ty = tid >> 4;
    const int rowBase = blockIdx.y * 64;
    float acc[4][4] = {};

    const int lr = tid >> 2;
    const int lc = (tid & 3) * 4;
    const int br = tid >> 4;         // 0..15
    const int bc = (tid & 15) * 4;   // 0..60

    for (int k0 = 0; k0 < SCFG; k0 += 16) {
        {
            float4 av = *reinterpret_cast<const float4*>(Ab + (size_t)(rowBase + lr) * SCFG + k0 + lc);
            As[lc + 0][lr] = av.x; As[lc + 1][lr] = av.y;
            As[lc + 2][lr] = av.z; As[lc + 3][lr] = av.w;
            float4 bv = *reinterpret_cast<const float4*>(Bv + (size_t)(k0 + br) * DCFG + bc);
            *reinterpret_cast<float4*>(&Bs[br][bc]) = bv;
        }
        __syncthreads();
#pragma unroll
        for (int kk = 0; kk < 16; ++kk) {
            const float4 a0 = *reinterpret_cast<const float4*>(&As[kk][ty * 4]);
            const float4 w0 = *reinterpret_cast<const float4*>(&Bs[kk][tx * 4]);
            const float a[4] = {a0.x, a0.y, a0.z, a0.w};
            const float w[4] = {w0.x, w0.y, w0.z, w0.w};
#pragma unroll
            for (int i = 0; i < 4; ++i)
#pragma unroll
                for (int j = 0; j < 4; ++j)
                    acc[i][j] = fmaf(a[i], w[j], acc[i][j]);
        }
        __syncthreads();
    }

#pragma unroll
    for (int i = 0; i < 4; ++i) {
        const int s = rowBase + ty * 4 + i;
#pragma unroll
        for (int j = 0; j < 4; ++j) {
            const int dcol = tx * 4 + j;
            vals[((size_t)(b * SCFG + s)) * ECFG + h * DCFG + dcol] = acc[i][j];
        }
    }
}

// ---------------- vqc: shifted-A GEMM + exact GELU + permuted store ----------
__global__ void __launch_bounds__(256) vqc_kernel(const float* __restrict__ h1,
                                                  const float* __restrict__ W,
                                                  const float* __restrict__ bias,
                                                  float* __restrict__ Z) {
    __shared__ float As[16][68];
    __shared__ float Ws[16][68];
    const int qi = blockIdx.z;                 // 0..3 (slice offset)
    const float* Ab = h1 + qi;                 // misaligned by qi -> scalar loads
    const int tid = threadIdx.x;
    const int tx = tid & 15, ty = tid >> 4;
    const int rowBase = blockIdx.y * 64;
    const int colBase = blockIdx.x * 64;
    float acc[4][4] = {};
    const int lr = tid >> 2;
    const int lc = (tid & 3) * 4;

    for (int k0 = 0; k0 < MCFG; k0 += 16) {
        {
            const int gr = rowBase + lr;
            const float* arow = Ab + (size_t)gr * H1LD + k0 + lc;
#pragma unroll
            for (int u = 0; u < 4; ++u) As[lc + u][lr] = arow[u];
            const int gw = colBase + lr;
            float4 wv = *reinterpret_cast<const float4*>(W + (size_t)gw * MCFG + k0 + lc);
            Ws[lc + 0][lr] = wv.x; Ws[lc + 1][lr] = wv.y;
            Ws[lc + 2][lr] = wv.z; Ws[lc + 3][lr] = wv.w;
        }
        __syncthreads();
#pragma unroll
        for (int kk = 0; kk < 16; ++kk) {
            const float4 a0 = *reinterpret_cast<const float4*>(&As[kk][ty * 4]);
            const float4 w0 = *reinterpret_cast<const float4*>(&Ws[kk][tx * 4]);
            const float a[4] = {a0.x, a0.y, a0.z, a0.w};
            const float w[4] = {w0.x, w0.y, w0.z, w0.w};
#pragma unroll
            for (int i = 0; i < 4; ++i)
#pragma unroll
                for (int j = 0; j < 4; ++j)
                    acc[i][j] = fmaf(a[i], w[j], acc[i][j]);
        }
        __syncthreads();
    }

#pragma unroll
    for (int i = 0; i < 4; ++i) {
        const int gr = rowBase + ty * 4 + i;
#pragma unroll
        for (int j = 0; j < 4; ++j) {
            const int gc = colBase + tx * 4 + j;       // m index
            float v = acc[i][j] + bias[gc];
            const float g = 0.5f * v * (1.0f + erff(v * 0.70710678118654752f));
            Z[(size_t)gr * QMCFG + gc * 4 + qi] = g;   // permute(0,1,3,2) layout
        }
    }
}

// ---------------- launch ----------------
extern "C" void kernel_launch(void* const* d_in, const int* in_sizes, int n_in,
                              void* d_out, int out_size) {
    const float* x     = (const float*)d_in[0];
    const float* ln1_w = (const float*)d_in[1];
    const float* ln1_b = (const float*)d_in[2];
    const float* Wq    = (const float*)d_in[3];
    const float* bq    = (const float*)d_in[4];
    const float* Wk    = (const float*)d_in[5];
    const float* bk    = (const float*)d_in[6];
    const float* Wv    = (const float*)d_in[7];
    const float* bv    = (const float*)d_in[8];
    const float* Wo    = (const float*)d_in[9];
    const float* bo    = (const float*)d_in[10];
    const float* pond  = (const float*)d_in[11];
    const float* ln2_w = (const float*)d_in[12];
    const float* ln2_b = (const float*)d_in[13];
    const float* fc1_W = (const float*)d_in[14];
    const float* fc1_b = (const float*)d_in[15];
    const float* vqc_W = (const float*)d_in[16];
    const float* vqc_b = (const float*)d_in[17];
    const float* fc2_W = (const float*)d_in[18];
    const float* fc2_b = (const float*)d_in[19];
    float* out = (float*)d_out;

    float *p_h, *p_q, *p_k, *p_v, *p_qn, *p_kn, *p_P, *p_vals, *p_x1, *p_y, *p_h1, *p_z;
    cudaGetSymbolAddress((void**)&p_h,    g_h);
    cudaGetSymbolAddress((void**)&p_q,    g_q);
    cudaGetSymbolAddress((void**)&p_k,    g_k);
    cudaGetSymbolAddress((void**)&p_v,    g_v);
    cudaGetSymbolAddress((void**)&p_qn,   g_qn);
    cudaGetSymbolAddress((void**)&p_kn,   g_kn);
    cudaGetSymbolAddress((void**)&p_P,    g_P);
    cudaGetSymbolAddress((void**)&p_vals, g_vals);
    cudaGetSymbolAddress((void**)&p_x1,   g_x1);
    cudaGetSymbolAddress((void**)&p_y,    g_y);
    cudaGetSymbolAddress((void**)&p_h1,   g_h1);
    cudaGetSymbolAddress((void**)&p_z,    g_z);

    // 1) LN1
    ln_kernel<<<NTOK, 256>>>(x, ln1_w, ln1_b, p_h);

    // 2) QKV GEMMs -> [bh, s, d] layout
    {
        dim3 g(ECFG / 64, NTOK / 64, 1);
        gemm_nt<<<g, 256>>>(p_h, ECFG, 0, Wq, ECFG, 0, bq, nullptr, 0,
                            p_q, 0, 0, NTOK, ECFG, ECFG, 1);
        gemm_nt<<<g, 256>>>(p_h, ECFG, 0, Wk, ECFG, 0, bk, nullptr, 0,
                            p_k, 0, 0, NTOK, ECFG, ECFG, 1);
        gemm_nt<<<g, 256>>>(p_h, ECFG, 0, Wv, ECFG, 0, bv, nullptr, 0,
                            p_v, 0, 0, NTOK, ECFG, ECFG, 1);
    }

    // 3) q/k row norms
    norm_kernel<<<(BHCFG * SCFG + 255) / 256, 256>>>(p_q, p_qn, BHCFG * SCFG);
    norm_kernel<<<(BHCFG * SCFG + 255) / 256, 256>>>(p_k, p_kn, BHCFG * SCFG);

    // 4) raw dot logits: P[bh][i][j] = q_i . k_j  (batched over bh)
    {
        dim3 g(SCFG / 64, SCFG / 64, BHCFG);
        gemm_nt<<<g, 256>>>(p_q, DCFG, (long long)SCFG * DCFG,
                            p_k, DCFG, (long long)SCFG * DCFG,
                            nullptr, nullptr, 0,
                            p_P, SCFG, (long long)SCFG * SCFG,
                            SCFG, SCFG, DCFG, 0);
    }

    // 5) softmax + RBF blend (in place)
    mix_kernel<<<BHCFG * SCFG, 256>>>(p_P, p_qn, p_kn, pond);

    // 6) vals = P @ V  -> [B,S,E] layout
    gemm_pv<<<dim3(1, SCFG / 64, BHCFG), 256>>>(p_P, p_v, p_vals);

    // 7) x1 = x + vals @ Wo^T + bo
    gemm_nt<<<dim3(ECFG / 64, NTOK / 64, 1), 256>>>(
        p_vals, ECFG, 0, Wo, ECFG, 0, bo, x, ECFG,
        p_x1, ECFG, 0, NTOK, ECFG, ECFG, 0);

    // 8) LN2
    ln_kernel<<<NTOK, 256>>>(p_x1, ln2_w, ln2_b, p_y);

    // 9) fc1 — only first 771 columns are consumed by the overlapping slices
    gemm_nt<<<dim3((H1C + 63) / 64, NTOK / 64, 1), 256>>>(
        p_y, ECFG, 0, fc1_W, ECFG, 0, fc1_b, nullptr, 0,
        p_h1, H1LD, 0, NTOK, H1C, ECFG, 0);

    // 10) vqc on 4 shifted slices + GELU + permuted store
    vqc_kernel<<<dim3(MCFG / 64, NTOK / 64, 4), 256>>>(p_h1, vqc_W, vqc_b, p_z);

    // 11) out = x1 + z @ fc2_W^T + fc2_b
    gemm_nt<<<dim3(ECFG / 64, NTOK / 64, 1), 256>>>(
        p_z, QMCFG, 0, fc2_W, QMCFG, 0, fc2_b, p_x1, ECFG,
        out, ECFG, 0, NTOK, ECFG, QMCFG, 0);

    (void)in_sizes; (void)n_in; (void)out_size;
}

// round 2
// speedup vs baseline: 1.0541x; 1.0541x over previous
#include <cuda_runtime.h>
#include <math.h>

// ---------------- problem constants ----------------
#define NTOK   2048          // B*S
#define ECFG   768
#define SCFG   1024
#define HCFG   12
#define DCFG   64
#define BHCFG  24            // B*H
#define MCFG   768
#define QMCFG  3072          // Q*M
#define H1C    771           // used fc1 columns (M + Q - 1)
#define H1LD   772           // padded stride

// ---------------- scratch (device globals; no allocs allowed) ----------------
__device__ float g_h   [NTOK * ECFG];
__device__ float g_q   [BHCFG * SCFG * DCFG];
__device__ float g_k   [BHCFG * SCFG * DCFG];
__device__ float g_v   [BHCFG * SCFG * DCFG];
__device__ float g_qn  [BHCFG * SCFG];
__device__ float g_kn  [BHCFG * SCFG];
__device__ float g_P   [(size_t)BHCFG * SCFG * SCFG];   // raw dots -> mixed probs
__device__ float g_vals[NTOK * ECFG];
__device__ float g_x1  [NTOK * ECFG];
__device__ float g_y   [NTOK * ECFG];
__device__ float g_h1  [NTOK * H1LD];
__device__ float g_z   [NTOK * QMCFG];

// ---------------- block reductions (blockDim.x == 256) ----------------
__device__ __forceinline__ float block_reduce_sum(float v, float* sbuf) {
#pragma unroll
    for (int o = 16; o > 0; o >>= 1) v += __shfl_xor_sync(0xffffffffu, v, o);
    int w = threadIdx.x >> 5, l = threadIdx.x & 31;
    __syncthreads();
    if (l == 0) sbuf[w] = v;
    __syncthreads();
    if (threadIdx.x < 32) {
        float t = (l < 8) ? sbuf[l] : 0.f;
#pragma unroll
        for (int o = 4; o > 0; o >>= 1) t += __shfl_xor_sync(0xffffffffu, t, o);
        if (l == 0) sbuf[32] = t;
    }
    __syncthreads();
    return sbuf[32];
}

__device__ __forceinline__ float block_reduce_max(float v, float* sbuf) {
#pragma unroll
    for (int o = 16; o > 0; o >>= 1) v = fmaxf(v, __shfl_xor_sync(0xffffffffu, v, o));
    int w = threadIdx.x >> 5, l = threadIdx.x & 31;
    __syncthreads();
    if (l == 0) sbuf[w] = v;
    __syncthreads();
    if (threadIdx.x < 32) {
        float t = (l < 8) ? sbuf[l] : -1e30f;
#pragma unroll
        for (int o = 4; o > 0; o >>= 1) t = fmaxf(t, __shfl_xor_sync(0xffffffffu, t, o));
        if (l == 0) sbuf[32] = t;
    }
    __syncthreads();
    return sbuf[32];
}

// ---------------- layernorm: one block per row of 768 ----------------
__global__ void __launch_bounds__(256) ln_kernel(const float* __restrict__ x,
                                                 const float* __restrict__ w,
                                                 const float* __restrict__ b,
                                                 float* __restrict__ out) {
    __shared__ float sbuf[34];
    const int row = blockIdx.x;
    const float* xr = x + (size_t)row * ECFG;
    float v[3];
    float s = 0.f, sq = 0.f;
#pragma unroll
    for (int u = 0; u < 3; ++u) {
        v[u] = xr[threadIdx.x + u * 256];
        s += v[u];
        sq += v[u] * v[u];
    }
    s  = block_reduce_sum(s, sbuf);
    sq = block_reduce_sum(sq, sbuf);
    const float mean = s * (1.0f / ECFG);
    const float var  = sq * (1.0f / ECFG) - mean * mean;
    const float inv  = rsqrtf(var + 1e-5f);
    float* orow = out + (size_t)row * ECFG;
#pragma unroll
    for (int u = 0; u < 3; ++u) {
        int e = threadIdx.x + u * 256;
        orow[e] = (v[u] - mean) * inv * w[e] + b[e];
    }
}

// ---------------- generic GEMM: C[n,co] = sum_k A[n,k]*W[co,k] (+bias)(+resid) ----
// 64x64 tile, BK=16, 256 threads, 4x4 per-thread microtile, float4 smem fragments.
// outMode 0: C[z*sCb + n*ldc + co]
// outMode 1: "bhsd" remap -> C[((b*12+h)*1024+s)*64+d]  (z==0 only)
__global__ void __launch_bounds__(256) gemm_nt(
    const float* __restrict__ A, int lda, long long sAb,
    const float* __restrict__ W, int ldw, long long sWb,
    const float* __restrict__ bias,
    const float* __restrict__ resid, int ldr,
    float* __restrict__ C, int ldc, long long sCb,
    int N, int Co, int K, int outMode)
{
    __shared__ float As[16][68];
    __shared__ float Ws[16][68];
    const int tid = threadIdx.x;
    const int tx = tid & 15, ty = tid >> 4;
    const int rowBase = blockIdx.y * 64;
    const int colBase = blockIdx.x * 64;
    const float* Ab = A + (size_t)blockIdx.z * sAb;
    const float* Wb = W + (size_t)blockIdx.z * sWb;
    float acc[4][4] = {};

    const int lr = tid >> 2;        // 0..63
    const int lc = (tid & 3) * 4;   // 0,4,8,12

    for (int k0 = 0; k0 < K; k0 += 16) {
        {
            const int gr = rowBase + lr;
            float4 av = make_float4(0.f, 0.f, 0.f, 0.f);
            if (gr < N) av = *reinterpret_cast<const float4*>(Ab + (size_t)gr * lda + k0 + lc);
            As[lc + 0][lr] = av.x; As[lc + 1][lr] = av.y;
            As[lc + 2][lr] = av.z; As[lc + 3][lr] = av.w;
            const int gw = colBase + lr;
            float4 wv = make_float4(0.f, 0.f, 0.f, 0.f);
            if (gw < Co) wv = *reinterpret_cast<const float4*>(Wb + (size_t)gw * ldw + k0 + lc);
            Ws[lc + 0][lr] = wv.x; Ws[lc + 1][lr] = wv.y;
            Ws[lc + 2][lr] = wv.z; Ws[lc + 3][lr] = wv.w;
        }
        __syncthreads();
#pragma unroll
        for (int kk = 0; kk < 16; ++kk) {
            const float4 a0 = *reinterpret_cast<const float4*>(&As[kk][ty * 4]);
            const float4 w0 = *reinterpret_cast<const float4*>(&Ws[kk][tx * 4]);
            const float a[4] = {a0.x, a0.y, a0.z, a0.w};
            const float w[4] = {w0.x, w0.y, w0.z, w0.w};
#pragma unroll
            for (int i = 0; i < 4; ++i)
#pragma unroll
                for (int j = 0; j < 4; ++j)
                    acc[i][j] = fmaf(a[i], w[j], acc[i][j]);
        }
        __syncthreads();
    }

#pragma unroll
    for (int i = 0; i < 4; ++i) {
        const int gr = rowBase + ty * 4 + i;
        if (gr >= N) continue;
#pragma unroll
        for (int j = 0; j < 4; ++j) {
            const int gc = colBase + tx * 4 + j;
            if (gc >= Co) continue;
            float v = acc[i][j];
            if (bias)  v += bias[gc];
            if (resid) v += resid[(size_t)gr * ldr + gc];
            if (outMode == 0) {
                C[(size_t)blockIdx.z * sCb + (size_t)gr * ldc + gc] = v;
            } else {
                const int b = gr >> 10, s = gr & 1023;
                const int h = gc >> 6, d = gc & 63;
                C[(((size_t)(b * HCFG + h)) * SCFG + s) * DCFG + d] = v;
            }
        }
    }
}

// ---------------- row norms of [rows][64] ----------------
__global__ void norm_kernel(const float* __restrict__ src, float* __restrict__ dst, int nrows) {
    const int r = blockIdx.x * blockDim.x + threadIdx.x;
    if (r >= nrows) return;
    const float4* p = reinterpret_cast<const float4*>(src + (size_t)r * DCFG);
    float s = 0.f;
#pragma unroll
    for (int i = 0; i < 16; ++i) {
        float4 t = p[i];
        s += t.x * t.x + t.y * t.y + t.z * t.z + t.w * t.w;
    }
    dst[r] = s;
}

// ---------------- softmax + RBF mix, in place on raw dot rows ----------------
__global__ void __launch_bounds__(256) mix_kernel(float* __restrict__ P,
                                                  const float* __restrict__ qn_,
                                                  const float* __restrict__ kn_,
                                                  const float* __restrict__ pond) {
    __shared__ float sbuf[34];
    const int row = blockIdx.x;             // bh*1024 + i
    const int bh  = row >> 10;
    float* prow = P + (size_t)row * SCFG;
    const float* knb = kn_ + (size_t)bh * SCFG;
    const int tid = threadIdx.x;

    const float qn = qn_[row];
    const float sigma2 = fminf(fmaxf(qn, 1e-8f), 1e4f);

    float4 dt  = *reinterpret_cast<const float4*>(prow + tid * 4);
    float4 kn4 = *reinterpret_cast<const float4*>(knb + tid * 4);
    const float d[4]  = {dt.x, dt.y, dt.z, dt.w};
    const float kn[4] = {kn4.x, kn4.y, kn4.z, kn4.w};

    float lm = -1e30f;
#pragma unroll
    for (int u = 0; u < 4; ++u) lm = fmaxf(lm, d[u] * 0.125f);
    const float M = block_reduce_max(lm, sbuf);

    float e[4], rb[4];
    float se = 0.f, sr = 0.f;
#pragma unroll
    for (int u = 0; u < 4; ++u) {
        e[u] = expf(d[u] * 0.125f - M);
        se += e[u];
        const float d2 = fmaxf(qn + kn[u] - 2.f * d[u], 0.f);
        rb[u] = expf(-d2 / sigma2);
        sr += rb[u];
    }
    const float Ls = block_reduce_sum(se, sbuf);
    const float Lr = block_reduce_sum(sr, sbuf);

    const float sv = 1.f / (1.f + expf(-pond[0]));
    const float p0 = 1.f - sv, p1 = sv;
    const float inv = 1.f / (p0 + p1 + 1e-7f);
    const float ca = p0 * inv / Ls;
    const float cb = p1 * inv / fmaxf(Lr, 1e-8f);

    float4 o;
    o.x = ca * e[0] + cb * rb[0];
    o.y = ca * e[1] + cb * rb[1];
    o.z = ca * e[2] + cb * rb[2];
    o.w = ca * e[3] + cb * rb[3];
    *reinterpret_cast<float4*>(prow + tid * 4) = o;
}

// ---------------- P @ V (B non-transposed), per (b,h) batch ----------------
__global__ void __launch_bounds__(256) gemm_pv(const float* __restrict__ P,
                                               const float* __restrict__ V,
                                               float* __restrict__ vals) {
    __shared__ float As[16][68];
    __shared__ float Bs[16][68];
    const int bh = blockIdx.z;
    const int b = bh / HCFG, h = bh % HCFG;
    const float* Ab = P + ((size_t)bh << 20);          // bh * 1024 * 1024
    const float* Bv = V + (size_t)bh * SCFG * DCFG;    // [1024][64]
    const int tid = threadIdx.x;
    const int tx = tid & 15, ty = tid >> 4;
    const int rowBase = blockIdx.y * 64;
    float acc[4][4] = {};

    const int lr = tid >> 2;
    const int lc = (tid & 3) * 4;
    const int br = tid >> 4;         // 0..15
    const int bc = (tid & 15) * 4;   // 0..60

    for (int k0 = 0; k0 < SCFG; k0 += 16) {
        {
            float4 av = *reinterpret_cast<const float4*>(Ab + (size_t)(rowBase + lr) * SCFG + k0 + lc);
            As[lc + 0][lr] = av.x; As[lc + 1][lr] = av.y;
            As[lc + 2][lr] = av.z; As[lc + 3][lr] = av.w;
            float4 bv = *reinterpret_cast<const float4*>(Bv + (size_t)(k0 + br) * DCFG + bc);
            *reinterpret_cast<float4*>(&Bs[br][bc]) = bv;
        }
        __syncthreads();
#pragma unroll
        for (int kk = 0; kk < 16; ++kk) {
            const float4 a0 = *reinterpret_cast<const float4*>(&As[kk][ty * 4]);
            const float4 w0 = *reinterpret_cast<const float4*>(&Bs[kk][tx * 4]);
            const float a[4] = {a0.x, a0.y, a0.z, a0.w};
            const float w[4] = {w0.x, w0.y, w0.z, w0.w};
#pragma unroll
            for (int i = 0; i < 4; ++i)
#pragma unroll
                for (int j = 0; j < 4; ++j)
                    acc[i][j] = fmaf(a[i], w[j], acc[i][j]);
        }
        __syncthreads();
    }

#pragma unroll
    for (int i = 0; i < 4; ++i) {
        const int s = rowBase + ty * 4 + i;
#pragma unroll
        for (int j = 0; j < 4; ++j) {
            const int dcol = tx * 4 + j;
            vals[((size_t)(b * SCFG + s)) * ECFG + h * DCFG + dcol] = acc[i][j];
        }
    }
}

// ---------------- vqc: shifted-A GEMM + exact GELU + permuted store ----------
__global__ void __launch_bounds__(256) vqc_kernel(const float* __restrict__ h1,
                                                  const float* __restrict__ W,
                                                  const float* __restrict__ bias,
                                                  float* __restrict__ Z) {
    __shared__ float As[16][68];
    __shared__ float Ws[16][68];
    const int qi = blockIdx.z;                 // 0..3 (slice offset)
    const float* Ab = h1 + qi;                 // misaligned by qi -> scalar loads
    const int tid = threadIdx.x;
    const int tx = tid & 15, ty = tid >> 4;
    const int rowBase = blockIdx.y * 64;
    const int colBase = blockIdx.x * 64;
    float acc[4][4] = {};
    const int lr = tid >> 2;
    const int lc = (tid & 3) * 4;

    for (int k0 = 0; k0 < MCFG; k0 += 16) {
        {
            const int gr = rowBase + lr;
            const float* arow = Ab + (size_t)gr * H1LD + k0 + lc;
#pragma unroll
            for (int u = 0; u < 4; ++u) As[lc + u][lr] = arow[u];
            const int gw = colBase + lr;
            float4 wv = *reinterpret_cast<const float4*>(W + (size_t)gw * MCFG + k0 + lc);
            Ws[lc + 0][lr] = wv.x; Ws[lc + 1][lr] = wv.y;
            Ws[lc + 2][lr] = wv.z; Ws[lc + 3][lr] = wv.w;
        }
        __syncthreads();
#pragma unroll
        for (int kk = 0; kk < 16; ++kk) {
            const float4 a0 = *reinterpret_cast<const float4*>(&As[kk][ty * 4]);
            const float4 w0 = *reinterpret_cast<const float4*>(&Ws[kk][tx * 4]);
            const float a[4] = {a0.x, a0.y, a0.z, a0.w};
            const float w[4] = {w0.x, w0.y, w0.z, w0.w};
#pragma unroll
            for (int i = 0; i < 4; ++i)
#pragma unroll
                for (int j = 0; j < 4; ++j)
                    acc[i][j] = fmaf(a[i], w[j], acc[i][j]);
        }
        __syncthreads();
    }

#pragma unroll
    for (int i = 0; i < 4; ++i) {
        const int gr = rowBase + ty * 4 + i;
#pragma unroll
        for (int j = 0; j < 4; ++j) {
            const int gc = colBase + tx * 4 + j;       // m index
            float v = acc[i][j] + bias[gc];
            const float g = 0.5f * v * (1.0f + erff(v * 0.70710678118654752f));
            Z[(size_t)gr * QMCFG + gc * 4 + qi] = g;   // permute(0,1,3,2) layout
        }
    }
}

// ---------------- launch ----------------
extern "C" void kernel_launch(void* const* d_in, const int* in_sizes, int n_in,
                              void* d_out, int out_size) {
    const float* x     = (const float*)d_in[0];
    const float* ln1_w = (const float*)d_in[1];
    const float* ln1_b = (const float*)d_in[2];
    const float* Wq    = (const float*)d_in[3];
    const float* bq    = (const float*)d_in[4];
    const float* Wk    = (const float*)d_in[5];
    const float* bk    = (const float*)d_in[6];
    const float* Wv    = (const float*)d_in[7];
    const float* bv    = (const float*)d_in[8];
    const float* Wo    = (const float*)d_in[9];
    const float* bo    = (const float*)d_in[10];
    const float* pond  = (const float*)d_in[11];
    const float* ln2_w = (const float*)d_in[12];
    const float* ln2_b = (const float*)d_in[13];
    const float* fc1_W = (const float*)d_in[14];
    const float* fc1_b = (const float*)d_in[15];
    const float* vqc_W = (const float*)d_in[16];
    const float* vqc_b = (const float*)d_in[17];
    const float* fc2_W = (const float*)d_in[18];
    const float* fc2_b = (const float*)d_in[19];
    float* out = (float*)d_out;

    float *p_h, *p_q, *p_k, *p_v, *p_qn, *p_kn, *p_P, *p_vals, *p_x1, *p_y, *p_h1, *p_z;
    cudaGetSymbolAddress((void**)&p_h,    g_h);
    cudaGetSymbolAddress((void**)&p_q,    g_q);
    cudaGetSymbolAddress((void**)&p_k,    g_k);
    cudaGetSymbolAddress((void**)&p_v,    g_v);
    cudaGetSymbolAddress((void**)&p_qn,   g_qn);
    cudaGetSymbolAddress((void**)&p_kn,   g_kn);
    cudaGetSymbolAddress((void**)&p_P,    g_P);
    cudaGetSymbolAddress((void**)&p_vals, g_vals);
    cudaGetSymbolAddress((void**)&p_x1,   g_x1);
    cudaGetSymbolAddress((void**)&p_y,    g_y);
    cudaGetSymbolAddress((void**)&p_h1,   g_h1);
    cudaGetSymbolAddress((void**)&p_z,    g_z);

    // 1) LN1
    ln_kernel<<<NTOK, 256>>>(x, ln1_w, ln1_b, p_h);

    // 2) QKV GEMMs -> [bh, s, d] layout
    {
        dim3 g(ECFG / 64, NTOK / 64, 1);
        gemm_nt<<<g, 256>>>(p_h, ECFG, 0, Wq, ECFG, 0, bq, nullptr, 0,
                            p_q, 0, 0, NTOK, ECFG, ECFG, 1);
        gemm_nt<<<g, 256>>>(p_h, ECFG, 0, Wk, ECFG, 0, bk, nullptr, 0,
                            p_k, 0, 0, NTOK, ECFG, ECFG, 1);
        gemm_nt<<<g, 256>>>(p_h, ECFG, 0, Wv, ECFG, 0, bv, nullptr, 0,
                            p_v, 0, 0, NTOK, ECFG, ECFG, 1);
    }

    // 3) q/k row norms
    norm_kernel<<<(BHCFG * SCFG + 255) / 256, 256>>>(p_q, p_qn, BHCFG * SCFG);
    norm_kernel<<<(BHCFG * SCFG + 255) / 256, 256>>>(p_k, p_kn, BHCFG * SCFG);

    // 4) raw dot logits: P[bh][i][j] = q_i . k_j  (batched over bh)
    {
        dim3 g(SCFG / 64, SCFG / 64, BHCFG);
        gemm_nt<<<g, 256>>>(p_q, DCFG, (long long)SCFG * DCFG,
                            p_k, DCFG, (long long)SCFG * DCFG,
                            nullptr, nullptr, 0,
                            p_P, SCFG, (long long)SCFG * SCFG,
                            SCFG, SCFG, DCFG, 0);
    }

    // 5) softmax + RBF blend (in place)
    mix_kernel<<<BHCFG * SCFG, 256>>>(p_P, p_qn, p_kn, pond);

    // 6) vals = P @ V  -> [B,S,E] layout
    gemm_pv<<<dim3(1, SCFG / 64, BHCFG), 256>>>(p_P, p_v, p_vals);

    // 7) x1 = x + vals @ Wo^T + bo
    gemm_nt<<<dim3(ECFG / 64, NTOK / 64, 1), 256>>>(
        p_vals, ECFG, 0, Wo, ECFG, 0, bo, x, ECFG,
        p_x1, ECFG, 0, NTOK, ECFG, ECFG, 0);

    // 8) LN2
    ln_kernel<<<NTOK, 256>>>(p_x1, ln2_w, ln2_b, p_y);

    // 9) fc1 — only first 771 columns are consumed by the overlapping slices
    gemm_nt<<<dim3((H1C + 63) / 64, NTOK / 64, 1), 256>>>(
        p_y, ECFG, 0, fc1_W, ECFG, 0, fc1_b, nullptr, 0,
        p_h1, H1LD, 0, NTOK, H1C, ECFG, 0);

    // 10) vqc on 4 shifted slices + GELU + permuted store
    vqc_kernel<<<dim3(MCFG / 64, NTOK / 64, 4), 256>>>(p_h1, vqc_W, vqc_b, p_z);

    // 11) out = x1 + z @ fc2_W^T + fc2_b
    gemm_nt<<<dim3(ECFG / 64, NTOK / 64, 1), 256>>>(
        p_z, QMCFG, 0, fc2_W, QMCFG, 0, fc2_b, p_x1, ECFG,
        out, ECFG, 0, NTOK, ECFG, QMCFG, 0);

    (void)in_sizes; (void)n_in; (void)out_size;
}

// round 5
// speedup vs baseline: 1.3213x; 1.2535x over previous
#include <cuda_runtime.h>
#include <cuda_bf16.h>
#include <cstdint>
#include <math.h>

#define NTOK   2048
#define ECFG   768
#define SCFG   1024
#define HCFG   12
#define DCFG   64
#define BHCFG  24
#define QMCFG  3072
#define H1C    771
#define H1W    772            // h1 pair-word row stride

// ---------------- scratch: pair buffers are uint32 {hi,lo} per fp32 elem ----
__device__ uint32_t g_h4   [(size_t)NTOK * ECFG];
__device__ uint32_t g_wqkv [(size_t)2304 * ECFG];
__device__ float    g_bqkv [2304];
__device__ float    g_q    [BHCFG * SCFG * DCFG];
__device__ float    g_k    [BHCFG * SCFG * DCFG];
__device__ float    g_v    [BHCFG * SCFG * DCFG];
__device__ float    g_qn   [BHCFG * SCFG];
__device__ float    g_kn   [BHCFG * SCFG];
__device__ float    g_P    [(size_t)BHCFG * SCFG * SCFG];
__device__ uint32_t g_vals [(size_t)NTOK * ECFG];
__device__ uint32_t g_wo   [(size_t)ECFG * ECFG];
__device__ float    g_x1   [NTOK * ECFG];
__device__ uint32_t g_y4   [(size_t)NTOK * ECFG];
__device__ uint32_t g_w1   [(size_t)896 * ECFG];
__device__ uint32_t g_h1   [(size_t)NTOK * H1W];
__device__ uint32_t g_wvq  [(size_t)ECFG * ECFG];
__device__ uint32_t g_z    [(size_t)NTOK * QMCFG];
__device__ uint32_t g_w2   [(size_t)ECFG * QMCFG];

// ---------------- helpers ----------------
__device__ __forceinline__ uint32_t smem_u32(const void* p) {
    uint32_t a;
    asm("{ .reg .u64 t; cvta.to.shared.u64 t, %1; cvt.u32.u64 %0, t; }" : "=r"(a) : "l"(p));
    return a;
}
__device__ __forceinline__ uint32_t pairW(float x) {
    __nv_bfloat16 h = __float2bfloat16(x);
    __nv_bfloat16 l = __float2bfloat16(x - __bfloat162float(h));
    return (uint32_t)__bfloat16_as_ushort(h) | ((uint32_t)__bfloat16_as_ushort(l) << 16);
}
__device__ __forceinline__ uint32_t prmt_(uint32_t a, uint32_t sel) {
    uint32_t d;
    asm("prmt.b32 %0, %1, %1, %2;" : "=r"(d) : "r"(a), "r"(sel));
    return d;
}
__device__ __forceinline__ void ldsm4(uint32_t* r, uint32_t addr) {
    asm volatile("ldmatrix.sync.aligned.m8n8.x4.shared.b16 {%0,%1,%2,%3}, [%4];"
        : "=r"(r[0]), "=r"(r[1]), "=r"(r[2]), "=r"(r[3]) : "r"(addr));
}
__device__ __forceinline__ void mma16816(float* c, const uint32_t* a, const uint32_t* b) {
    asm volatile("mma.sync.aligned.m16n8k16.row.col.f32.bf16.bf16.f32 "
        "{%0,%1,%2,%3}, {%4,%5,%6,%7}, {%8,%9}, {%0,%1,%2,%3};"
        : "+f"(c[0]), "+f"(c[1]), "+f"(c[2]), "+f"(c[3])
        : "r"(a[0]), "r"(a[1]), "r"(a[2]), "r"(a[3]), "r"(b[0]), "r"(b[1]));
}

// weight conversion to pair words; rows >= inRows zeroed
__global__ void __launch_bounds__(256) convPair(const float* __restrict__ in, int ldi, int Kc,
                                                uint32_t* __restrict__ out, int ldo, int inRows) {
    const int k = blockIdx.x * 256 + threadIdx.x;
    const int r = blockIdx.y;
    if (k >= Kc) return;
    out[(size_t)r * ldo + k] = (r < inRows) ? pairW(in[(size_t)r * ldi + k]) : 0u;
}

__global__ void bcat_kernel(const float* __restrict__ a, const float* __restrict__ b,
                            const float* __restrict__ c, float* __restrict__ o) {
    int t = blockIdx.x * 256 + threadIdx.x;
    if (t < 768) o[t] = a[t];
    else if (t < 1536) o[t] = b[t - 768];
    else if (t < 2304) o[t] = c[t - 1536];
}

// ---------------- block reductions ----------------
__device__ __forceinline__ float bred_sum(float v, float* sbuf) {
#pragma unroll
    for (int o = 16; o > 0; o >>= 1) v += __shfl_xor_sync(0xffffffffu, v, o);
    int w = threadIdx.x >> 5, l = threadIdx.x & 31;
    __syncthreads();
    if (l == 0) sbuf[w] = v;
    __syncthreads();
    if (threadIdx.x < 32) {
        float t = (l < 8) ? sbuf[l] : 0.f;
#pragma unroll
        for (int o = 4; o > 0; o >>= 1) t += __shfl_xor_sync(0xffffffffu, t, o);
        if (l == 0) sbuf[32] = t;
    }
    __syncthreads();
    return sbuf[32];
}
__device__ __forceinline__ float bred_max(float v, float* sbuf) {
#pragma unroll
    for (int o = 16; o > 0; o >>= 1) v = fmaxf(v, __shfl_xor_sync(0xffffffffu, v, o));
    int w = threadIdx.x >> 5, l = threadIdx.x & 31;
    __syncthreads();
    if (l == 0) sbuf[w] = v;
    __syncthreads();
    if (threadIdx.x < 32) {
        float t = (l < 8) ? sbuf[l] : -1e30f;
#pragma unroll
        for (int o = 4; o > 0; o >>= 1) t = fmaxf(t, __shfl_xor_sync(0xffffffffu, t, o));
        if (l == 0) sbuf[32] = t;
    }
    __syncthreads();
    return sbuf[32];
}

// ---------------- layernorm -> fp32 pair words ----------------
__global__ void __launch_bounds__(256) ln_pair(const float* __restrict__ x,
                                               const float* __restrict__ w,
                                               const float* __restrict__ b,
                                               uint32_t* __restrict__ out) {
    __shared__ float sbuf[34];
    const int row = blockIdx.x;
    const float* xr = x + (size_t)row * ECFG;
    float v[3];
    float s = 0.f, sq = 0.f;
#pragma unroll
    for (int u = 0; u < 3; ++u) {
        v[u] = xr[threadIdx.x + u * 256];
        s += v[u];
        sq += v[u] * v[u];
    }
    s  = bred_sum(s, sbuf);
    sq = bred_sum(sq, sbuf);
    const float mean = s * (1.0f / ECFG);
    const float inv  = rsqrtf(sq * (1.0f / ECFG) - mean * mean + 1e-5f);
    uint32_t* orow = out + (size_t)row * ECFG;
#pragma unroll
    for (int u = 0; u < 3; ++u) {
        int e = threadIdx.x + u * 256;
        orow[e] = pairW((v[u] - mean) * inv * w[e] + b[e]);
    }
}

// ================= HMMA GEMM =================
// C tile 128x128 = A_pair . B_pair^T with exact hi/lo quad split, fp32 accum.
// A-pattern per orig k: {hi,lo,hi,lo}; B-pattern: {hi,hi,lo,lo}. 8 warps, 64x32/warp.
// mode 0: C0[gr*ldc+gc] = acc + bias (+resid[gr*ldc+gc])
// mode 1: QKV -> bhsd into C0/C1/C2
// mode 2: vqc: +bias, GELU -> Cq[gr*3072 + gc*4 + qi] pair
// mode 3: fc1: +bias -> Cq[gr*772 + gc] pair, gc < colLimit
__global__ void __launch_bounds__(256) hm_gemm(
    const uint32_t* __restrict__ Ap, int ldaW,
    const uint32_t* __restrict__ Bp, int ldbW,
    const float* __restrict__ bias, const float* __restrict__ resid,
    float* __restrict__ C0, float* __restrict__ C1, float* __restrict__ C2,
    uint32_t* __restrict__ Cq, int ldc, int Kc, int mode, int colLimit)
{
    __shared__ __align__(16) uint32_t As[128 * 36];
    __shared__ __align__(16) uint32_t Bs[128 * 36];
    const int t = threadIdx.x;
    const int lane = t & 31, wid = t >> 5;
    const int rowBase = blockIdx.y * 128;
    const int colBase = blockIdx.x * 128;
    const int qi = blockIdx.z;
    if (mode == 2) Ap += qi;               // word offset (4B) -> scalar loads below
    const int mBase = (wid >> 2) * 64;
    const int nBase = (wid & 3) * 32;

    float acc[4][4][4] = {};

    // staging mapping
    const int srow = t >> 1, half = t & 1;
    const uint32_t* aSrc = Ap + (size_t)(rowBase + srow) * ldaW + half * 8;
    const uint32_t* bSrc = Bp + (size_t)(colBase + srow) * ldbW + half * 8;
    uint4* As4 = reinterpret_cast<uint4*>(As) + srow * 9 + half * 4;
    uint4* Bs4 = reinterpret_cast<uint4*>(Bs) + srow * 9 + half * 4;

    // ldmatrix addressing
    const uint32_t asBase = smem_u32(As), bsBase = smem_u32(Bs);
    const int mat = lane >> 3, lr8 = lane & 7;
    const int rOff = (mat & 1) * 8 + lr8;
    const int cByte = (mat >> 1) * 16;
    uint32_t aAddr[4], bAddr[2];
#pragma unroll
    for (int a = 0; a < 4; ++a) aAddr[a] = asBase + (uint32_t)((mBase + a * 16 + rOff) * 144 + cByte);
#pragma unroll
    for (int bp = 0; bp < 2; ++bp) bAddr[bp] = bsBase + (uint32_t)((nBase + bp * 16 + rOff) * 144 + cByte);

    const int NIT = Kc >> 4;
    for (int it = 0; it < NIT; ++it) {
        uint32_t aw[8], bw[8];
        if (mode == 2) {
#pragma unroll
            for (int j = 0; j < 8; ++j) aw[j] = aSrc[(size_t)it * 16 + j];
        } else {
            uint4 t0 = *reinterpret_cast<const uint4*>(aSrc + (size_t)it * 16);
            uint4 t1 = *reinterpret_cast<const uint4*>(aSrc + (size_t)it * 16 + 4);
            aw[0] = t0.x; aw[1] = t0.y; aw[2] = t0.z; aw[3] = t0.w;
            aw[4] = t1.x; aw[5] = t1.y; aw[6] = t1.z; aw[7] = t1.w;
        }
        {
            uint4 t0 = *reinterpret_cast<const uint4*>(bSrc + (size_t)it * 16);
            uint4 t1 = *reinterpret_cast<const uint4*>(bSrc + (size_t)it * 16 + 4);
            bw[0] = t0.x; bw[1] = t0.y; bw[2] = t0.z; bw[3] = t0.w;
            bw[4] = t1.x; bw[5] = t1.y; bw[6] = t1.z; bw[7] = t1.w;
        }
        __syncthreads();
#pragma unroll
        for (int j = 0; j < 4; ++j) {
            As4[j] = make_uint4(aw[2 * j], aw[2 * j], aw[2 * j + 1], aw[2 * j + 1]);
            Bs4[j] = make_uint4(prmt_(bw[2 * j], 0x1010u), prmt_(bw[2 * j], 0x3232u),
                                prmt_(bw[2 * j + 1], 0x1010u), prmt_(bw[2 * j + 1], 0x3232u));
        }
        __syncthreads();
#pragma unroll
        for (int s = 0; s < 4; ++s) {
            uint32_t bf[4][2];
#pragma unroll
            for (int bp = 0; bp < 2; ++bp) {
                uint32_t r4[4];
                ldsm4(r4, bAddr[bp] + s * 32);
                bf[2 * bp][0] = r4[0]; bf[2 * bp + 1][0] = r4[1];
                bf[2 * bp][1] = r4[2]; bf[2 * bp + 1][1] = r4[3];
            }
#pragma unroll
            for (int a = 0; a < 4; ++a) {
                uint32_t af[4];
                ldsm4(af, aAddr[a] + s * 32);
#pragma unroll
                for (int bn = 0; bn < 4; ++bn)
                    mma16816(acc[a][bn], af, bf[bn]);
            }
        }
    }

    // ---------------- epilogue ----------------
    const int r = lane >> 2, cp = (lane & 3) * 2;
#pragma unroll
    for (int a = 0; a < 4; ++a) {
#pragma unroll
        for (int bn = 0; bn < 4; ++bn) {
            const float* c = acc[a][bn];
            const int gc = colBase + nBase + bn * 8 + cp;
            const float b0 = bias[gc], b1 = bias[gc + 1];
#pragma unroll
            for (int hh = 0; hh < 2; ++hh) {
                const int gr = rowBase + mBase + a * 16 + r + hh * 8;
                float v0 = c[hh * 2] + b0, v1 = c[hh * 2 + 1] + b1;
                if (mode == 0) {
                    if (resid) {
                        v0 += resid[(size_t)gr * ldc + gc];
                        v1 += resid[(size_t)gr * ldc + gc + 1];
                    }
                    *reinterpret_cast<float2*>(C0 + (size_t)gr * ldc + gc) = make_float2(v0, v1);
                } else if (mode == 1) {
                    const int which = (gc >= 1536) ? 2 : (gc >= 768 ? 1 : 0);
                    const int e = gc - which * 768;
                    float* dst = which == 0 ? C0 : (which == 1 ? C1 : C2);
                    const int bb = gr >> 10, s = gr & 1023;
                    *reinterpret_cast<float2*>(
                        dst + (((size_t)(bb * HCFG + (e >> 6))) * SCFG + s) * DCFG + (e & 63)) =
                        make_float2(v0, v1);
                } else if (mode == 2) {
                    const float g0 = 0.5f * v0 * (1.0f + erff(v0 * 0.70710678118654752f));
                    const float g1 = 0.5f * v1 * (1.0f + erff(v1 * 0.70710678118654752f));
                    Cq[(size_t)gr * QMCFG + (size_t)gc * 4 + qi] = pairW(g0);
                    Cq[(size_t)gr * QMCFG + (size_t)(gc + 1) * 4 + qi] = pairW(g1);
                } else {
                    if (gc < colLimit)     Cq[(size_t)gr * H1W + gc]     = pairW(v0);
                    if (gc + 1 < colLimit) Cq[(size_t)gr * H1W + gc + 1] = pairW(v1);
                }
            }
        }
    }
}

// ---------------- SIMT logits GEMM: P[bh][i][j] = q_i . k_j ----------------
__global__ void __launch_bounds__(256) gemm_qk(const float* __restrict__ Q,
                                               const float* __restrict__ Km,
                                               float* __restrict__ P) {
    __shared__ float As[16][68];
    __shared__ float Ws[16][68];
    const int bh = blockIdx.z;
    const float* Ab = Q + (size_t)bh * SCFG * DCFG;
    const float* Wb = Km + (size_t)bh * SCFG * DCFG;
    float* Cb = P + ((size_t)bh << 20);
    const int t = threadIdx.x;
    const int tx = t & 15, ty = t >> 4;
    const int rowBase = blockIdx.y * 64, colBase = blockIdx.x * 64;
    float acc[4][4] = {};
    const int lr = t >> 2, lc = (t & 3) * 4;

    for (int k0 = 0; k0 < DCFG; k0 += 16) {
        float4 av = *reinterpret_cast<const float4*>(Ab + (size_t)(rowBase + lr) * DCFG + k0 + lc);
        As[lc + 0][lr] = av.x; As[lc + 1][lr] = av.y; As[lc + 2][lr] = av.z; As[lc + 3][lr] = av.w;
        float4 wv = *reinterpret_cast<const float4*>(Wb + (size_t)(colBase + lr) * DCFG + k0 + lc);
        Ws[lc + 0][lr] = wv.x; Ws[lc + 1][lr] = wv.y; Ws[lc + 2][lr] = wv.z; Ws[lc + 3][lr] = wv.w;
        __syncthreads();
#pragma unroll
        for (int kk = 0; kk < 16; ++kk) {
            const float4 a0 = *reinterpret_cast<const float4*>(&As[kk][ty * 4]);
            const float4 w0 = *reinterpret_cast<const float4*>(&Ws[kk][tx * 4]);
#pragma unroll
            for (int i = 0; i < 4; ++i) {
                const float ai = (&a0.x)[i];
#pragma unroll
                for (int j = 0; j < 4; ++j)
                    acc[i][j] = fmaf(ai, (&w0.x)[j], acc[i][j]);
            }
        }
        __syncthreads();
    }
#pragma unroll
    for (int i = 0; i < 4; ++i)
#pragma unroll
        for (int j = 0; j < 4; ++j)
            Cb[(size_t)(rowBase + ty * 4 + i) * SCFG + colBase + tx * 4 + j] = acc[i][j];
}

// ---------------- row norms ----------------
__global__ void norm_kernel(const float* __restrict__ src, float* __restrict__ dst, int nrows) {
    const int r = blockIdx.x * blockDim.x + threadIdx.x;
    if (r >= nrows) return;
    const float4* p = reinterpret_cast<const float4*>(src + (size_t)r * DCFG);
    float s = 0.f;
#pragma unroll
    for (int i = 0; i < 16; ++i) {
        float4 t = p[i];
        s += t.x * t.x + t.y * t.y + t.z * t.z + t.w * t.w;
    }
    dst[r] = s;
}

// ---------------- softmax + RBF mix ----------------
__global__ void __launch_bounds__(256) mix_kernel(float* __restrict__ P,
                                                  const float* __restrict__ qn_,
                                                  const float* __restrict__ kn_,
                                                  const float* __restrict__ pond) {
    __shared__ float sbuf[34];
    const int row = blockIdx.x;
    const int bh  = row >> 10;
    float* prow = P + (size_t)row * SCFG;
    const float* knb = kn_ + (size_t)bh * SCFG;
    const int tid = threadIdx.x;
    const float qn = qn_[row];
    const float sigma2 = fminf(fmaxf(qn, 1e-8f), 1e4f);

    float4 dt  = *reinterpret_cast<const float4*>(prow + tid * 4);
    float4 kn4 = *reinterpret_cast<const float4*>(knb + tid * 4);
    const float d[4]  = {dt.x, dt.y, dt.z, dt.w};
    const float kn[4] = {kn4.x, kn4.y, kn4.z, kn4.w};

    float lm = -1e30f;
#pragma unroll
    for (int u = 0; u < 4; ++u) lm = fmaxf(lm, d[u] * 0.125f);
    const float M = bred_max(lm, sbuf);

    float e[4], rb[4];
    float se = 0.f, sr = 0.f;
#pragma unroll
    for (int u = 0; u < 4; ++u) {
        e[u] = expf(d[u] * 0.125f - M);
        se += e[u];
        const float d2 = fmaxf(qn + kn[u] - 2.f * d[u], 0.f);
        rb[u] = expf(-d2 / sigma2);
        sr += rb[u];
    }
    const float Ls = bred_sum(se, sbuf);
    const float Lr = bred_sum(sr, sbuf);

    const float sv = 1.f / (1.f + expf(-pond[0]));
    const float p0 = 1.f - sv, p1 = sv;
    const float inv = 1.f / (p0 + p1 + 1e-7f);
    const float ca = p0 * inv / Ls;
    const float cb = p1 * inv / fmaxf(Lr, 1e-8f);

    float4 o;
    o.x = ca * e[0] + cb * rb[0];
    o.y = ca * e[1] + cb * rb[1];
    o.z = ca * e[2] + cb * rb[2];
    o.w = ca * e[3] + cb * rb[3];
    *reinterpret_cast<float4*>(prow + tid * 4) = o;
}

// ---------------- P @ V -> vals pair words ----------------
__global__ void __launch_bounds__(256) gemm_pv(const float* __restrict__ P,
                                               const float* __restrict__ V,
                                               uint32_t* __restrict__ vals) {
    __shared__ float As[16][68];
    __shared__ float Bs[16][68];
    const int bh = blockIdx.z;
    const int b = bh / HCFG, h = bh % HCFG;
    const float* Ab = P + ((size_t)bh << 20);
    const float* Bv = V + (size_t)bh * SCFG * DCFG;
    const int t = threadIdx.x;
    const int tx = t & 15, ty = t >> 4;
    const int rowBase = blockIdx.y * 64;
    float acc[4][4] = {};
    const int lr = t >> 2, lc = (t & 3) * 4;
    const int br = t >> 4, bc = (t & 15) * 4;

    for (int k0 = 0; k0 < SCFG; k0 += 16) {
        float4 av = *reinterpret_cast<const float4*>(Ab + (size_t)(rowBase + lr) * SCFG + k0 + lc);
        As[lc + 0][lr] = av.x; As[lc + 1][lr] = av.y; As[lc + 2][lr] = av.z; As[lc + 3][lr] = av.w;
        *reinterpret_cast<float4*>(&Bs[br][bc]) =
            *reinterpret_cast<const float4*>(Bv + (size_t)(k0 + br) * DCFG + bc);
        __syncthreads();
#pragma unroll
        for (int kk = 0; kk < 16; ++kk) {
            const float4 a0 = *reinterpret_cast<const float4*>(&As[kk][ty * 4]);
            const float4 w0 = *reinterpret_cast<const float4*>(&Bs[kk][tx * 4]);
#pragma unroll
            for (int i = 0; i < 4; ++i) {
                const float ai = (&a0.x)[i];
#pragma unroll
                for (int j = 0; j < 4; ++j)
                    acc[i][j] = fmaf(ai, (&w0.x)[j], acc[i][j]);
            }
        }
        __syncthreads();
    }
#pragma unroll
    for (int i = 0; i < 4; ++i) {
        const int s = rowBase + ty * 4 + i;
        uint32_t* orow = vals + ((size_t)(b * SCFG + s)) * ECFG;
#pragma unroll
        for (int j = 0; j < 4; ++j)
            orow[h * DCFG + tx * 4 + j] = pairW(acc[i][j]);
    }
}

// ---------------- launch ----------------
extern "C" void kernel_launch(void* const* d_in, const int* in_sizes, int n_in,
                              void* d_out, int out_size) {
    const float* x     = (const float*)d_in[0];
    const float* ln1_w = (const float*)d_in[1];
    const float* ln1_b = (const float*)d_in[2];
    const float* Wq    = (const float*)d_in[3];
    const float* bq    = (const float*)d_in[4];
    const float* Wk    = (const float*)d_in[5];
    const float* bk    = (const float*)d_in[6];
    const float* Wv    = (const float*)d_in[7];
    const float* bv    = (const float*)d_in[8];
    const float* Wo    = (const float*)d_in[9];
    const float* bo    = (const float*)d_in[10];
    const float* pond  = (const float*)d_in[11];
    const float* ln2_w = (const float*)d_in[12];
    const float* ln2_b = (const float*)d_in[13];
    const float* fc1_W = (const float*)d_in[14];
    const float* fc1_b = (const float*)d_in[15];
    const float* vqc_W = (const float*)d_in[16];
    const float* vqc_b = (const float*)d_in[17];
    const float* fc2_W = (const float*)d_in[18];
    const float* fc2_b = (const float*)d_in[19];
    float* out = (float*)d_out;

    float *p_q, *p_k, *p_v, *p_qn, *p_kn, *p_P, *p_x1, *p_bqkv;
    uint32_t *p_h4, *p_wqkv, *p_vals, *p_wo, *p_y4, *p_w1, *p_h1, *p_wvq, *p_z, *p_w2;
    cudaGetSymbolAddress((void**)&p_h4,   g_h4);
    cudaGetSymbolAddress((void**)&p_wqkv, g_wqkv);
    cudaGetSymbolAddress((void**)&p_bqkv, g_bqkv);
    cudaGetSymbolAddress((void**)&p_q,    g_q);
    cudaGetSymbolAddress((void**)&p_k,    g_k);
    cudaGetSymbolAddress((void**)&p_v,    g_v);
    cudaGetSymbolAddress((void**)&p_qn,   g_qn);
    cudaGetSymbolAddress((void**)&p_kn,   g_kn);
    cudaGetSymbolAddress((void**)&p_P,    g_P);
    cudaGetSymbolAddress((void**)&p_vals, g_vals);
    cudaGetSymbolAddress((void**)&p_wo,   g_wo);
    cudaGetSymbolAddress((void**)&p_x1,   g_x1);
    cudaGetSymbolAddress((void**)&p_y4,   g_y4);
    cudaGetSymbolAddress((void**)&p_w1,   g_w1);
    cudaGetSymbolAddress((void**)&p_h1,   g_h1);
    cudaGetSymbolAddress((void**)&p_wvq,  g_wvq);
    cudaGetSymbolAddress((void**)&p_z,    g_z);
    cudaGetSymbolAddress((void**)&p_w2,   g_w2);

    // weight conversions (pair words)
    convPair<<<dim3(3, 768), 256>>>(Wq, ECFG, ECFG, p_wqkv, ECFG, 768);
    convPair<<<dim3(3, 768), 256>>>(Wk, ECFG, ECFG, p_wqkv + (size_t)768 * ECFG, ECFG, 768);
    convPair<<<dim3(3, 768), 256>>>(Wv, ECFG, ECFG, p_wqkv + (size_t)1536 * ECFG, ECFG, 768);
    convPair<<<dim3(3, 768), 256>>>(Wo, ECFG, ECFG, p_wo, ECFG, 768);
    convPair<<<dim3(3, 896), 256>>>(fc1_W, ECFG, ECFG, p_w1, ECFG, H1C);
    convPair<<<dim3(3, 768), 256>>>(vqc_W, 768, 768, p_wvq, ECFG, 768);
    convPair<<<dim3(12, 768), 256>>>(fc2_W, QMCFG, QMCFG, p_w2, QMCFG, 768);
    bcat_kernel<<<9, 256>>>(bq, bk, bv, p_bqkv);

    // 1) LN1 -> h pair
    ln_pair<<<NTOK, 256>>>(x, ln1_w, ln1_b, p_h4);

    // 2) fused QKV (HMMA) -> q/k/v bhsd fp32
    hm_gemm<<<dim3(18, 16), 256>>>(p_h4, ECFG, p_wqkv, ECFG, p_bqkv, nullptr,
                                   p_q, p_k, p_v, nullptr, 0, 768, 1, 0);

    // 3) norms
    norm_kernel<<<(BHCFG * SCFG + 255) / 256, 256>>>(p_q, p_qn, BHCFG * SCFG);
    norm_kernel<<<(BHCFG * SCFG + 255) / 256, 256>>>(p_k, p_kn, BHCFG * SCFG);

    // 4) logits (SIMT)
    gemm_qk<<<dim3(16, 16, BHCFG), 256>>>(p_q, p_k, p_P);

    // 5) softmax + RBF
    mix_kernel<<<BHCFG * SCFG, 256>>>(p_P, p_qn, p_kn, pond);

    // 6) P @ V -> vals pair
    gemm_pv<<<dim3(1, 16, BHCFG), 256>>>(p_P, p_v, p_vals);

    // 7) x1 = x + vals@Wo^T + bo (HMMA)
    hm_gemm<<<dim3(6, 16), 256>>>(p_vals, ECFG, p_wo, ECFG, bo, x,
                                  p_x1, nullptr, nullptr, nullptr, ECFG, 768, 0, 0);

    // 8) LN2 -> y pair
    ln_pair<<<NTOK, 256>>>(p_x1, ln2_w, ln2_b, p_y4);

    // 9) fc1 (771 cols) -> h1 pair (HMMA)
    hm_gemm<<<dim3(7, 16), 256>>>(p_y4, ECFG, p_w1, ECFG, fc1_b, nullptr,
                                  nullptr, nullptr, nullptr, p_h1, 0, 768, 3, H1C);

    // 10) vqc + GELU -> z pair (HMMA, 4 shifted slices)
    hm_gemm<<<dim3(6, 16, 4), 256>>>(p_h1, H1W, p_wvq, ECFG, vqc_b, nullptr,
                                     nullptr, nullptr, nullptr, p_z, 0, 768, 2, 0);

    // 11) out = x1 + z@fc2^T + fc2_b (HMMA)
    hm_gemm<<<dim3(6, 16), 256>>>(p_z, QMCFG, p_w2, QMCFG, fc2_b, p_x1,
                                  out, nullptr, nullptr, nullptr, ECFG, 3072, 0, 0);

    (void)in_sizes; (void)n_in; (void)out_size;
}

// round 6
// speedup vs baseline: 1.6533x; 1.2512x over previous
#include <cuda_runtime.h>
#include <cuda_bf16.h>
#include <cstdint>
#include <math.h>

#define NTOK   2048
#define ECFG   768
#define SCFG   1024
#define HCFG   12
#define DCFG   64
#define BHCFG  24
#define QMCFG  3072
#define H1C    771
#define H1W    772            // h1 pair-word row stride

// ---------------- scratch: pair buffers are uint32 {hi,lo} per fp32 elem ----
__device__ uint32_t g_h4   [(size_t)NTOK * ECFG];
__device__ uint32_t g_wqkv [(size_t)2304 * ECFG];
__device__ float    g_bqkv [2304];
__device__ uint32_t g_qp   [(size_t)BHCFG * SCFG * DCFG];   // q pair [bh][s][d]
__device__ uint32_t g_kp   [(size_t)BHCFG * SCFG * DCFG];   // k pair [bh][s][d]
__device__ uint32_t g_vt   [(size_t)BHCFG * DCFG * SCFG];   // v pair transposed [bh][d][s]
__device__ float    g_qn   [BHCFG * SCFG];
__device__ float    g_kn   [BHCFG * SCFG];
__device__ float    g_P    [(size_t)BHCFG * SCFG * SCFG];   // raw dots fp32 -> pair words
__device__ uint32_t g_vals [(size_t)NTOK * ECFG];
__device__ uint32_t g_wo   [(size_t)ECFG * ECFG];
__device__ float    g_x1   [NTOK * ECFG];
__device__ uint32_t g_y4   [(size_t)NTOK * ECFG];
__device__ uint32_t g_w1   [(size_t)896 * ECFG];
__device__ uint32_t g_h1   [(size_t)NTOK * H1W];
__device__ uint32_t g_wvq  [(size_t)ECFG * ECFG];
__device__ uint32_t g_z    [(size_t)NTOK * QMCFG];
__device__ uint32_t g_w2   [(size_t)ECFG * QMCFG];

// ---------------- helpers ----------------
__device__ __forceinline__ uint32_t smem_u32(const void* p) {
    uint32_t a;
    asm("{ .reg .u64 t; cvta.to.shared.u64 t, %1; cvt.u32.u64 %0, t; }" : "=r"(a) : "l"(p));
    return a;
}
__device__ __forceinline__ uint32_t pairW(float x) {
    __nv_bfloat16 h = __float2bfloat16(x);
    __nv_bfloat16 l = __float2bfloat16(x - __bfloat162float(h));
    return (uint32_t)__bfloat16_as_ushort(h) | ((uint32_t)__bfloat16_as_ushort(l) << 16);
}
__device__ __forceinline__ float unpairW(uint32_t w) {
    __nv_bfloat16 h = __ushort_as_bfloat16((unsigned short)(w & 0xffffu));
    __nv_bfloat16 l = __ushort_as_bfloat16((unsigned short)(w >> 16));
    return __bfloat162float(h) + __bfloat162float(l);
}
__device__ __forceinline__ uint32_t prmt_(uint32_t a, uint32_t sel) {
    uint32_t d;
    asm("prmt.b32 %0, %1, %1, %2;" : "=r"(d) : "r"(a), "r"(sel));
    return d;
}
__device__ __forceinline__ void ldsm4(uint32_t* r, uint32_t addr) {
    asm volatile("ldmatrix.sync.aligned.m8n8.x4.shared.b16 {%0,%1,%2,%3}, [%4];"
        : "=r"(r[0]), "=r"(r[1]), "=r"(r[2]), "=r"(r[3]) : "r"(addr));
}
__device__ __forceinline__ void mma16816(float* c, const uint32_t* a, const uint32_t* b) {
    asm volatile("mma.sync.aligned.m16n8k16.row.col.f32.bf16.bf16.f32 "
        "{%0,%1,%2,%3}, {%4,%5,%6,%7}, {%8,%9}, {%0,%1,%2,%3};"
        : "+f"(c[0]), "+f"(c[1]), "+f"(c[2]), "+f"(c[3])
        : "r"(a[0]), "r"(a[1]), "r"(a[2]), "r"(a[3]), "r"(b[0]), "r"(b[1]));
}

// weight conversion to pair words; rows >= inRows zeroed
__global__ void __launch_bounds__(256) convPair(const float* __restrict__ in, int ldi, int Kc,
                                                uint32_t* __restrict__ out, int ldo, int inRows) {
    const int k = blockIdx.x * 256 + threadIdx.x;
    const int r = blockIdx.y;
    if (k >= Kc) return;
    out[(size_t)r * ldo + k] = (r < inRows) ? pairW(in[(size_t)r * ldi + k]) : 0u;
}

__global__ void bcat_kernel(const float* __restrict__ a, const float* __restrict__ b,
                            const float* __restrict__ c, float* __restrict__ o) {
    int t = blockIdx.x * 256 + threadIdx.x;
    if (t < 768) o[t] = a[t];
    else if (t < 1536) o[t] = b[t - 768];
    else if (t < 2304) o[t] = c[t - 1536];
}

// ---------------- block reductions ----------------
__device__ __forceinline__ float bred_sum(float v, float* sbuf) {
#pragma unroll
    for (int o = 16; o > 0; o >>= 1) v += __shfl_xor_sync(0xffffffffu, v, o);
    int w = threadIdx.x >> 5, l = threadIdx.x & 31;
    __syncthreads();
    if (l == 0) sbuf[w] = v;
    __syncthreads();
    if (threadIdx.x < 32) {
        float t = (l < 8) ? sbuf[l] : 0.f;
#pragma unroll
        for (int o = 4; o > 0; o >>= 1) t += __shfl_xor_sync(0xffffffffu, t, o);
        if (l == 0) sbuf[32] = t;
    }
    __syncthreads();
    return sbuf[32];
}
__device__ __forceinline__ float bred_max(float v, float* sbuf) {
#pragma unroll
    for (int o = 16; o > 0; o >>= 1) v = fmaxf(v, __shfl_xor_sync(0xffffffffu, v, o));
    int w = threadIdx.x >> 5, l = threadIdx.x & 31;
    __syncthreads();
    if (l == 0) sbuf[w] = v;
    __syncthreads();
    if (threadIdx.x < 32) {
        float t = (l < 8) ? sbuf[l] : -1e30f;
#pragma unroll
        for (int o = 4; o > 0; o >>= 1) t = fmaxf(t, __shfl_xor_sync(0xffffffffu, t, o));
        if (l == 0) sbuf[32] = t;
    }
    __syncthreads();
    return sbuf[32];
}

// ---------------- layernorm -> fp32 pair words ----------------
__global__ void __launch_bounds__(256) ln_pair(const float* __restrict__ x,
                                               const float* __restrict__ w,
                                               const float* __restrict__ b,
                                               uint32_t* __restrict__ out) {
    __shared__ float sbuf[34];
    const int row = blockIdx.x;
    const float* xr = x + (size_t)row * ECFG;
    float v[3];
    float s = 0.f, sq = 0.f;
#pragma unroll
    for (int u = 0; u < 3; ++u) {
        v[u] = xr[threadIdx.x + u * 256];
        s += v[u];
        sq += v[u] * v[u];
    }
    s  = bred_sum(s, sbuf);
    sq = bred_sum(sq, sbuf);
    const float mean = s * (1.0f / ECFG);
    const float inv  = rsqrtf(sq * (1.0f / ECFG) - mean * mean + 1e-5f);
    uint32_t* orow = out + (size_t)row * ECFG;
#pragma unroll
    for (int u = 0; u < 3; ++u) {
        int e = threadIdx.x + u * 256;
        orow[e] = pairW((v[u] - mean) * inv * w[e] + b[e]);
    }
}

// ================= HMMA GEMM =================
// C tile 128x128 = A_pair . B_pair^T with exact hi/lo quad split, fp32 accum.
// A quad: {hi,lo,hi,lo}; B quad: {hi,hi,lo,lo}. 8 warps, 64x32/warp.
// mode 0: C0[gr*ldc+gc] = acc + bias (+resid)
// mode 1: QKV -> pair q/k [bh][s][d] into C0/C1, v transposed pair [bh][d][s] into C2
// mode 2: vqc: +bias, GELU -> Cq[gr*3072 + gc*4 + qi] pair
// mode 3: fc1: +bias -> Cq[gr*772 + gc] pair, gc < colLimit
// mode 4: logits batch z: A,B offset z*65536, C0 offset z<<20, raw fp32 store
__global__ void __launch_bounds__(256) hm_gemm(
    const uint32_t* __restrict__ Ap, int ldaW,
    const uint32_t* __restrict__ Bp, int ldbW,
    const float* __restrict__ bias, const float* __restrict__ resid,
    float* __restrict__ C0, float* __restrict__ C1, float* __restrict__ C2,
    uint32_t* __restrict__ Cq, int ldc, int Kc, int mode, int colLimit)
{
    __shared__ __align__(16) uint32_t As[128 * 36];
    __shared__ __align__(16) uint32_t Bs[128 * 36];
    const int t = threadIdx.x;
    const int lane = t & 31, wid = t >> 5;
    const int rowBase = blockIdx.y * 128;
    const int colBase = blockIdx.x * 128;
    const int qi = blockIdx.z;
    if (mode == 2) Ap += qi;
    if (mode == 4) {
        Ap += (size_t)qi << 16;
        Bp += (size_t)qi << 16;
        C0 += (size_t)qi << 20;
    }
    const int mBase = (wid >> 2) * 64;
    const int nBase = (wid & 3) * 32;

    float acc[4][4][4] = {};

    const int srow = t >> 1, half = t & 1;
    const uint32_t* aSrc = Ap + (size_t)(rowBase + srow) * ldaW + half * 8;
    const uint32_t* bSrc = Bp + (size_t)(colBase + srow) * ldbW + half * 8;
    uint4* As4 = reinterpret_cast<uint4*>(As) + srow * 9 + half * 4;
    uint4* Bs4 = reinterpret_cast<uint4*>(Bs) + srow * 9 + half * 4;

    const uint32_t asBase = smem_u32(As), bsBase = smem_u32(Bs);
    const int mat = lane >> 3, lr8 = lane & 7;
    const int rOff = (mat & 1) * 8 + lr8;
    const int cByte = (mat >> 1) * 16;
    uint32_t aAddr[4], bAddr[2];
#pragma unroll
    for (int a = 0; a < 4; ++a) aAddr[a] = asBase + (uint32_t)((mBase + a * 16 + rOff) * 144 + cByte);
#pragma unroll
    for (int bp = 0; bp < 2; ++bp) bAddr[bp] = bsBase + (uint32_t)((nBase + bp * 16 + rOff) * 144 + cByte);

    const int NIT = Kc >> 4;
    uint32_t aw[8], bw[8];

    // prefetch tile 0
    {
        if (mode == 2) {
#pragma unroll
            for (int j = 0; j < 8; ++j) aw[j] = aSrc[j];
        } else {
            uint4 t0 = *reinterpret_cast<const uint4*>(aSrc);
            uint4 t1 = *reinterpret_cast<const uint4*>(aSrc + 4);
            aw[0] = t0.x; aw[1] = t0.y; aw[2] = t0.z; aw[3] = t0.w;
            aw[4] = t1.x; aw[5] = t1.y; aw[6] = t1.z; aw[7] = t1.w;
        }
        uint4 t0 = *reinterpret_cast<const uint4*>(bSrc);
        uint4 t1 = *reinterpret_cast<const uint4*>(bSrc + 4);
        bw[0] = t0.x; bw[1] = t0.y; bw[2] = t0.z; bw[3] = t0.w;
        bw[4] = t1.x; bw[5] = t1.y; bw[6] = t1.z; bw[7] = t1.w;
    }

    for (int it = 0; it < NIT; ++it) {
        __syncthreads();   // previous compute done reading smem
#pragma unroll
        for (int j = 0; j < 4; ++j) {
            As4[j] = make_uint4(aw[2 * j], aw[2 * j], aw[2 * j + 1], aw[2 * j + 1]);
            Bs4[j] = make_uint4(prmt_(bw[2 * j], 0x1010u), prmt_(bw[2 * j], 0x3232u),
                                prmt_(bw[2 * j + 1], 0x1010u), prmt_(bw[2 * j + 1], 0x3232u));
        }
        __syncthreads();
        if (it + 1 < NIT) {   // prefetch next tile; latency hidden under compute
            const size_t o = (size_t)(it + 1) * 16;
            if (mode == 2) {
#pragma unroll
                for (int j = 0; j < 8; ++j) aw[j] = aSrc[o + j];
            } else {
                uint4 t0 = *reinterpret_cast<const uint4*>(aSrc + o);
                uint4 t1 = *reinterpret_cast<const uint4*>(aSrc + o + 4);
                aw[0] = t0.x; aw[1] = t0.y; aw[2] = t0.z; aw[3] = t0.w;
                aw[4] = t1.x; aw[5] = t1.y; aw[6] = t1.z; aw[7] = t1.w;
            }
            uint4 t0 = *reinterpret_cast<const uint4*>(bSrc + o);
            uint4 t1 = *reinterpret_cast<const uint4*>(bSrc + o + 4);
            bw[0] = t0.x; bw[1] = t0.y; bw[2] = t0.z; bw[3] = t0.w;
            bw[4] = t1.x; bw[5] = t1.y; bw[6] = t1.z; bw[7] = t1.w;
        }
#pragma unroll
        for (int s = 0; s < 4; ++s) {
            uint32_t bf[4][2];
#pragma unroll
            for (int bp = 0; bp < 2; ++bp) {
                uint32_t r4[4];
                ldsm4(r4, bAddr[bp] + s * 32);
                bf[2 * bp][0] = r4[0]; bf[2 * bp + 1][0] = r4[1];
                bf[2 * bp][1] = r4[2]; bf[2 * bp + 1][1] = r4[3];
            }
#pragma unroll
            for (int a = 0; a < 4; ++a) {
                uint32_t af[4];
                ldsm4(af, aAddr[a] + s * 32);
#pragma unroll
                for (int bn = 0; bn < 4; ++bn)
                    mma16816(acc[a][bn], af, bf[bn]);
            }
        }
    }

    // ---------------- epilogue ----------------
    const int r = lane >> 2, cp = (lane & 3) * 2;
#pragma unroll
    for (int a = 0; a < 4; ++a) {
#pragma unroll
        for (int bn = 0; bn < 4; ++bn) {
            const float* c = acc[a][bn];
            const int gc = colBase + nBase + bn * 8 + cp;
            const float b0 = bias ? bias[gc] : 0.f;
            const float b1 = bias ? bias[gc + 1] : 0.f;
#pragma unroll
            for (int hh = 0; hh < 2; ++hh) {
                const int gr = rowBase + mBase + a * 16 + r + hh * 8;
                float v0 = c[hh * 2] + b0, v1 = c[hh * 2 + 1] + b1;
                if (mode == 0) {
                    if (resid) {
                        v0 += resid[(size_t)gr * ldc + gc];
                        v1 += resid[(size_t)gr * ldc + gc + 1];
                    }
                    *reinterpret_cast<float2*>(C0 + (size_t)gr * ldc + gc) = make_float2(v0, v1);
                } else if (mode == 4) {
                    *reinterpret_cast<float2*>(C0 + (size_t)gr * ldc + gc) = make_float2(v0, v1);
                } else if (mode == 1) {
                    const int which = (gc >= 1536) ? 2 : (gc >= 768 ? 1 : 0);
                    const int e = gc - which * 768;
                    const int h = e >> 6, d = e & 63;
                    const int bb = gr >> 10, s = gr & 1023;
                    if (which < 2) {
                        uint32_t* dst = reinterpret_cast<uint32_t*>(which == 0 ? C0 : C1);
                        size_t base = (((size_t)(bb * HCFG + h)) * SCFG + s) * DCFG;
                        dst[base + d]     = pairW(v0);
                        dst[base + d + 1] = pairW(v1);
                    } else {
                        uint32_t* dst = reinterpret_cast<uint32_t*>(C2);
                        size_t base = ((size_t)(bb * HCFG + h)) * DCFG * SCFG;
                        dst[base + (size_t)d * SCFG + s]       = pairW(v0);
                        dst[base + (size_t)(d + 1) * SCFG + s] = pairW(v1);
                    }
                } else if (mode == 2) {
                    const float g0 = 0.5f * v0 * (1.0f + erff(v0 * 0.70710678118654752f));
                    const float g1 = 0.5f * v1 * (1.0f + erff(v1 * 0.70710678118654752f));
                    Cq[(size_t)gr * QMCFG + (size_t)gc * 4 + qi] = pairW(g0);
                    Cq[(size_t)gr * QMCFG + (size_t)(gc + 1) * 4 + qi] = pairW(g1);
                } else {
                    if (gc < colLimit)     Cq[(size_t)gr * H1W + gc]     = pairW(v0);
                    if (gc + 1 < colLimit) Cq[(size_t)gr * H1W + gc + 1] = pairW(v1);
                }
            }
        }
    }
}

// ================= PV HMMA: vals[i][d] = sum_j P[i][j] * Vt[d][j] =================
// M=128 x N=64 tile; 8 warps (4 m x 2 n), 32x32 per warp.
__global__ void __launch_bounds__(256) pv_gemm(const uint32_t* __restrict__ Pp,
                                               const uint32_t* __restrict__ Vt,
                                               uint32_t* __restrict__ vals) {
    __shared__ __align__(16) uint32_t As[128 * 36];
    __shared__ __align__(16) uint32_t Bs[64 * 36];
    const int t = threadIdx.x;
    const int lane = t & 31, wid = t >> 5;
    const int bh = blockIdx.y;
    const int rowBase = blockIdx.x * 128;
    const uint32_t* A = Pp + ((size_t)bh << 20);
    const uint32_t* B = Vt + (size_t)bh * DCFG * SCFG;
    const int mBase = (wid >> 1) * 32;
    const int nBase = (wid & 1) * 32;

    float acc[2][4][4] = {};

    const int srow = t >> 1, half = t & 1;
    const uint32_t* aSrc = A + (size_t)(rowBase + srow) * SCFG + half * 8;
    const int brow = (t & 127) >> 1;
    const uint32_t* bSrc = B + (size_t)brow * SCFG + half * 8;
    uint4* As4 = reinterpret_cast<uint4*>(As) + srow * 9 + half * 4;
    uint4* Bs4 = reinterpret_cast<uint4*>(Bs) + brow * 9 + half * 4;
    const bool doB = t < 128;

    const uint32_t asBase = smem_u32(As), bsBase = smem_u32(Bs);
    const int mat = lane >> 3, lr8 = lane & 7;
    const int rOff = (mat & 1) * 8 + lr8;
    const int cByte = (mat >> 1) * 16;
    uint32_t aAddr[2], bAddr[2];
#pragma unroll
    for (int a = 0; a < 2; ++a) aAddr[a] = asBase + (uint32_t)((mBase + a * 16 + rOff) * 144 + cByte);
#pragma unroll
    for (int bp = 0; bp < 2; ++bp) bAddr[bp] = bsBase + (uint32_t)((nBase + bp * 16 + rOff) * 144 + cByte);

    const int NIT = SCFG >> 4;   // 64 iterations of 16 pair words
    uint32_t aw[8], bw[8];
    {
        uint4 t0 = *reinterpret_cast<const uint4*>(aSrc);
        uint4 t1 = *reinterpret_cast<const uint4*>(aSrc + 4);
        aw[0] = t0.x; aw[1] = t0.y; aw[2] = t0.z; aw[3] = t0.w;
        aw[4] = t1.x; aw[5] = t1.y; aw[6] = t1.z; aw[7] = t1.w;
        if (doB) {
            uint4 s0 = *reinterpret_cast<const uint4*>(bSrc);
            uint4 s1 = *reinterpret_cast<const uint4*>(bSrc + 4);
            bw[0] = s0.x; bw[1] = s0.y; bw[2] = s0.z; bw[3] = s0.w;
            bw[4] = s1.x; bw[5] = s1.y; bw[6] = s1.z; bw[7] = s1.w;
        }
    }

    for (int it = 0; it < NIT; ++it) {
        __syncthreads();
#pragma unroll
        for (int j = 0; j < 4; ++j)
            As4[j] = make_uint4(aw[2 * j], aw[2 * j], aw[2 * j + 1], aw[2 * j + 1]);
        if (doB) {
#pragma unroll
            for (int j = 0; j < 4; ++j)
                Bs4[j] = make_uint4(prmt_(bw[2 * j], 0x1010u), prmt_(bw[2 * j], 0x3232u),
                                    prmt_(bw[2 * j + 1], 0x1010u), prmt_(bw[2 * j + 1], 0x3232u));
        }
        __syncthreads();
        if (it + 1 < NIT) {
            const size_t o = (size_t)(it + 1) * 16;
            uint4 t0 = *reinterpret_cast<const uint4*>(aSrc + o);
            uint4 t1 = *reinterpret_cast<const uint4*>(aSrc + o + 4);
            aw[0] = t0.x; aw[1] = t0.y; aw[2] = t0.z; aw[3] = t0.w;
            aw[4] = t1.x; aw[5] = t1.y; aw[6] = t1.z; aw[7] = t1.w;
            if (doB) {
                uint4 s0 = *reinterpret_cast<const uint4*>(bSrc + o);
                uint4 s1 = *reinterpret_cast<const uint4*>(bSrc + o + 4);
                bw[0] = s0.x; bw[1] = s0.y; bw[2] = s0.z; bw[3] = s0.w;
                bw[4] = s1.x; bw[5] = s1.y; bw[6] = s1.z; bw[7] = s1.w;
            }
        }
#pragma unroll
        for (int s = 0; s < 4; ++s) {
            uint32_t bf[4][2];
#pragma unroll
            for (int bp = 0; bp < 2; ++bp) {
                uint32_t r4[4];
                ldsm4(r4, bAddr[bp] + s * 32);
                bf[2 * bp][0] = r4[0]; bf[2 * bp + 1][0] = r4[1];
                bf[2 * bp][1] = r4[2]; bf[2 * bp + 1][1] = r4[3];
            }
#pragma unroll
            for (int a = 0; a < 2; ++a) {
                uint32_t af[4];
                ldsm4(af, aAddr[a] + s * 32);
#pragma unroll
                for (int bn = 0; bn < 4; ++bn)
                    mma16816(acc[a][bn], af, bf[bn]);
            }
        }
    }

    // epilogue -> vals pair [b*S+s][h*64+d]
    const int b = bh / HCFG, h = bh % HCFG;
    const int r = lane >> 2, cp = (lane & 3) * 2;
#pragma unroll
    for (int a = 0; a < 2; ++a) {
#pragma unroll
        for (int bn = 0; bn < 4; ++bn) {
            const float* c = acc[a][bn];
            const int d = nBase + bn * 8 + cp;
#pragma unroll
            for (int hh = 0; hh < 2; ++hh) {
                const int s = rowBase + mBase + a * 16 + r + hh * 8;
                uint32_t* orow = vals + ((size_t)(b * SCFG + s)) * ECFG + h * DCFG;
                orow[d]     = pairW(c[hh * 2]);
                orow[d + 1] = pairW(c[hh * 2 + 1]);
            }
        }
    }
}

// ---------------- row norms from pair words ----------------
__global__ void norm_pair(const uint32_t* __restrict__ src, float* __restrict__ dst, int nrows) {
    const int r = blockIdx.x * blockDim.x + threadIdx.x;
    if (r >= nrows) return;
    const uint4* p = reinterpret_cast<const uint4*>(src + (size_t)r * DCFG);
    float s = 0.f;
#pragma unroll
    for (int i = 0; i < 16; ++i) {
        uint4 t = p[i];
        float a = unpairW(t.x), b = unpairW(t.y), c = unpairW(t.z), d = unpairW(t.w);
        s += a * a + b * b + c * c + d * d;
    }
    dst[r] = s;
}

// ---------------- softmax + RBF mix: fp32 dots in, pair probs out (in place) ----
__global__ void __launch_bounds__(256) mix_kernel(float* __restrict__ P,
                                                  const float* __restrict__ qn_,
                                                  const float* __restrict__ kn_,
                                                  const float* __restrict__ pond) {
    __shared__ float sbuf[34];
    const int row = blockIdx.x;
    const int bh  = row >> 10;
    float* prow = P + (size_t)row * SCFG;
    const float* knb = kn_ + (size_t)bh * SCFG;
    const int tid = threadIdx.x;
    const float qn = qn_[row];
    const float sigma2 = fminf(fmaxf(qn, 1e-8f), 1e4f);

    float4 dt  = *reinterpret_cast<const float4*>(prow + tid * 4);
    float4 kn4 = *reinterpret_cast<const float4*>(knb + tid * 4);
    const float d[4]  = {dt.x, dt.y, dt.z, dt.w};
    const float kn[4] = {kn4.x, kn4.y, kn4.z, kn4.w};

    float lm = -1e30f;
#pragma unroll
    for (int u = 0; u < 4; ++u) lm = fmaxf(lm, d[u] * 0.125f);
    const float M = bred_max(lm, sbuf);

    float e[4], rb[4];
    float se = 0.f, sr = 0.f;
#pragma unroll
    for (int u = 0; u < 4; ++u) {
        e[u] = expf(d[u] * 0.125f - M);
        se += e[u];
        const float d2 = fmaxf(qn + kn[u] - 2.f * d[u], 0.f);
        rb[u] = expf(-d2 / sigma2);
        sr += rb[u];
    }
    const float Ls = bred_sum(se, sbuf);
    const float Lr = bred_sum(sr, sbuf);

    const float sv = 1.f / (1.f + expf(-pond[0]));
    const float p0 = 1.f - sv, p1 = sv;
    const float inv = 1.f / (p0 + p1 + 1e-7f);
    const float ca = p0 * inv / Ls;
    const float cb = p1 * inv / fmaxf(Lr, 1e-8f);

    uint4 o;
    o.x = pairW(ca * e[0] + cb * rb[0]);
    o.y = pairW(ca * e[1] + cb * rb[1]);
    o.z = pairW(ca * e[2] + cb * rb[2]);
    o.w = pairW(ca * e[3] + cb * rb[3]);
    *reinterpret_cast<uint4*>(prow + tid * 4) = o;
}

// ---------------- launch ----------------
extern "C" void kernel_launch(void* const* d_in, const int* in_sizes, int n_in,
                              void* d_out, int out_size) {
    const float* x     = (const float*)d_in[0];
    const float* ln1_w = (const float*)d_in[1];
    const float* ln1_b = (const float*)d_in[2];
    const float* Wq    = (const float*)d_in[3];
    const float* bq    = (const float*)d_in[4];
    const float* Wk    = (const float*)d_in[5];
    const float* bk    = (const float*)d_in[6];
    const float* Wv    = (const float*)d_in[7];
    const float* bv    = (const float*)d_in[8];
    const float* Wo    = (const float*)d_in[9];
    const float* bo    = (const float*)d_in[10];
    const float* pond  = (const float*)d_in[11];
    const float* ln2_w = (const float*)d_in[12];
    const float* ln2_b = (const float*)d_in[13];
    const float* fc1_W = (const float*)d_in[14];
    const float* fc1_b = (const float*)d_in[15];
    const float* vqc_W = (const float*)d_in[16];
    const float* vqc_b = (const float*)d_in[17];
    const float* fc2_W = (const float*)d_in[18];
    const float* fc2_b = (const float*)d_in[19];
    float* out = (float*)d_out;

    float *p_qn, *p_kn, *p_P, *p_x1, *p_bqkv;
    uint32_t *p_h4, *p_wqkv, *p_qp, *p_kp, *p_vt, *p_vals, *p_wo, *p_y4, *p_w1, *p_h1, *p_wvq, *p_z, *p_w2;
    cudaGetSymbolAddress((void**)&p_h4,   g_h4);
    cudaGetSymbolAddress((void**)&p_wqkv, g_wqkv);
    cudaGetSymbolAddress((void**)&p_bqkv, g_bqkv);
    cudaGetSymbolAddress((void**)&p_qp,   g_qp);
    cudaGetSymbolAddress((void**)&p_kp,   g_kp);
    cudaGetSymbolAddress((void**)&p_vt,   g_vt);
    cudaGetSymbolAddress((void**)&p_qn,   g_qn);
    cudaGetSymbolAddress((void**)&p_kn,   g_kn);
    cudaGetSymbolAddress((void**)&p_P,    g_P);
    cudaGetSymbolAddress((void**)&p_vals, g_vals);
    cudaGetSymbolAddress((void**)&p_wo,   g_wo);
    cudaGetSymbolAddress((void**)&p_x1,   g_x1);
    cudaGetSymbolAddress((void**)&p_y4,   g_y4);
    cudaGetSymbolAddress((void**)&p_w1,   g_w1);
    cudaGetSymbolAddress((void**)&p_h1,   g_h1);
    cudaGetSymbolAddress((void**)&p_wvq,  g_wvq);
    cudaGetSymbolAddress((void**)&p_z,    g_z);
    cudaGetSymbolAddress((void**)&p_w2,   g_w2);

    // weight conversions (pair words)
    convPair<<<dim3(3, 768), 256>>>(Wq, ECFG, ECFG, p_wqkv, ECFG, 768);
    convPair<<<dim3(3, 768), 256>>>(Wk, ECFG, ECFG, p_wqkv + (size_t)768 * ECFG, ECFG, 768);
    convPair<<<dim3(3, 768), 256>>>(Wv, ECFG, ECFG, p_wqkv + (size_t)1536 * ECFG, ECFG, 768);
    convPair<<<dim3(3, 768), 256>>>(Wo, ECFG, ECFG, p_wo, ECFG, 768);
    convPair<<<dim3(3, 896), 256>>>(fc1_W, ECFG, ECFG, p_w1, ECFG, H1C);
    convPair<<<dim3(3, 768), 256>>>(vqc_W, 768, 768, p_wvq, ECFG, 768);
    convPair<<<dim3(12, 768), 256>>>(fc2_W, QMCFG, QMCFG, p_w2, QMCFG, 768);
    bcat_kernel<<<9, 256>>>(bq, bk, bv, p_bqkv);

    // 1) LN1 -> h pair
    ln_pair<<<NTOK, 256>>>(x, ln1_w, ln1_b, p_h4);

    // 2) fused QKV (HMMA) -> q/k pair bhsd, v pair transposed
    hm_gemm<<<dim3(18, 16), 256>>>(p_h4, ECFG, p_wqkv, ECFG, p_bqkv, nullptr,
                                   (float*)p_qp, (float*)p_kp, (float*)p_vt, nullptr, 0, 768, 1, 0);

    // 3) norms from pair
    norm_pair<<<(BHCFG * SCFG + 255) / 256, 256>>>(p_qp, p_qn, BHCFG * SCFG);
    norm_pair<<<(BHCFG * SCFG + 255) / 256, 256>>>(p_kp, p_kn, BHCFG * SCFG);

    // 4) logits (HMMA split, exact) -> raw dots fp32
    hm_gemm<<<dim3(8, 8, BHCFG), 256>>>(p_qp, DCFG, p_kp, DCFG, nullptr, nullptr,
                                        p_P, nullptr, nullptr, nullptr, SCFG, 64, 4, 0);

    // 5) softmax + RBF -> P pair (in place)
    mix_kernel<<<BHCFG * SCFG, 256>>>(p_P, p_qn, p_kn, pond);

    // 6) P @ V (HMMA) -> vals pair
    pv_gemm<<<dim3(8, BHCFG), 256>>>((const uint32_t*)p_P, p_vt, p_vals);

    // 7) x1 = x + vals@Wo^T + bo (HMMA)
    hm_gemm<<<dim3(6, 16), 256>>>(p_vals, ECFG, p_wo, ECFG, bo, x,
                                  p_x1, nullptr, nullptr, nullptr, ECFG, 768, 0, 0);

    // 8) LN2 -> y pair
    ln_pair<<<NTOK, 256>>>(p_x1, ln2_w, ln2_b, p_y4);

    // 9) fc1 (771 cols) -> h1 pair (HMMA)
    hm_gemm<<<dim3(7, 16), 256>>>(p_y4, ECFG, p_w1, ECFG, fc1_b, nullptr,
                                  nullptr, nullptr, nullptr, p_h1, 0, 768, 3, H1C);

    // 10) vqc + GELU -> z pair (HMMA, 4 shifted slices)
    hm_gemm<<<dim3(6, 16, 4), 256>>>(p_h1, H1W, p_wvq, ECFG, vqc_b, nullptr,
                                     nullptr, nullptr, nullptr, p_z, 0, 768, 2, 0);

    // 11) out = x1 + z@fc2^T + fc2_b (HMMA)
    hm_gemm<<<dim3(6, 16), 256>>>(p_z, QMCFG, p_w2, QMCFG, fc2_b, p_x1,
                                  out, nullptr, nullptr, nullptr, ECFG, 3072, 0, 0);

    (void)in_sizes; (void)n_in; (void)out_size;
}